// round 9
// baseline (speedup 1.0000x reference)
#include <cuda_runtime.h>
#include <cuda_bf16.h>
#include <cstdint>
#include <cstddef>

// Problem constants
#define BATCH   2
#define SEQ     2048
#define EMBED   1024
#define HEADS   16
#define HDIM    64
#define MTOT    (BATCH * SEQ)          // 4096
#define OUT_ELEMS   ((size_t)BATCH * SEQ * EMBED)                    // 4,194,304

// Scratch
__device__ float g_Q[BATCH * HEADS * SEQ * HDIM];
__device__ float g_K[BATCH * HEADS * SEQ * HDIM];
__device__ float g_V[BATCH * HEADS * SEQ * HDIM];
__device__ float g_AO[BATCH * SEQ * EMBED];

// ===========================================================================
// helpers
// ===========================================================================
__device__ __forceinline__ uint32_t pack_bf16x2(__nv_bfloat16 a, __nv_bfloat16 b) {
    __nv_bfloat162 t;
    t.x = a; t.y = b;
    return *reinterpret_cast<uint32_t*>(&t);
}

// hi/lo split of a float4 -> two u32 each (pairs along k)
__device__ __forceinline__ void cvt_store_hl(uint32_t* hi, uint32_t* lo, float4 v) {
    __nv_bfloat16 hx = __float2bfloat16(v.x);
    __nv_bfloat16 hy = __float2bfloat16(v.y);
    __nv_bfloat16 hz = __float2bfloat16(v.z);
    __nv_bfloat16 hw = __float2bfloat16(v.w);
    hi[0] = pack_bf16x2(hx, hy);
    hi[1] = pack_bf16x2(hz, hw);
    lo[0] = pack_bf16x2(__float2bfloat16(v.x - __bfloat162float(hx)),
                        __float2bfloat16(v.y - __bfloat162float(hy)));
    lo[1] = pack_bf16x2(__float2bfloat16(v.z - __bfloat162float(hz)),
                        __float2bfloat16(v.w - __bfloat162float(hw)));
}

// mma.sync m16n8k16 bf16 -> f32, C += A*B
__device__ __forceinline__ void mma16816(float* c, const uint32_t* a, const uint32_t* b) {
    asm volatile(
        "mma.sync.aligned.m16n8k16.row.col.f32.bf16.bf16.f32 "
        "{%0,%1,%2,%3}, {%4,%5,%6,%7}, {%8,%9}, {%0,%1,%2,%3};\n"
        : "+f"(c[0]), "+f"(c[1]), "+f"(c[2]), "+f"(c[3])
        : "r"(a[0]), "r"(a[1]), "r"(a[2]), "r"(a[3]), "r"(b[0]), "r"(b[1]));
}

// smem row stride in u32 for BK=32 tiles: 16 data + 4 pad (conflict-free)
#define SK 20

// ===========================================================================
// Core split-bf16 GEMM tile: C[128, 64] = A[128, Kd] * B[64, Kd]^T
// 256 threads, 8 warps as 4m x 2n, warp tile 32x32. ~100 regs -> occ 2.
// mode 0: C[r*ldc+n] = acc + bias[n]
// mode 1: split-head store to [B,H,S,Dh], + bias[n]
// mode 2: C[r*ldc+n] = acc * scale           (no bias)
// ===========================================================================
__device__ __forceinline__ void gemm_core(
    const float* __restrict__ A, const float* __restrict__ B,
    const float* __restrict__ bias, float* __restrict__ C,
    int lda, int ldb, int ldc, int kdim, int mode, float scale,
    int bm, int bn)
{
    __shared__ uint32_t Ah[128 * SK], Al[128 * SK], Bh[64 * SK], Bl[64 * SK];

    const int tid = threadIdx.x;
    const int w   = tid >> 5;
    const int lid = tid & 31;
    const int g   = lid >> 2;      // 0..7
    const int tg  = lid & 3;       // 0..3
    const int wm  = w >> 1;        // 0..3
    const int wn  = w & 1;         // 0..1

    // A staging: 2 threads/row, 16 floats each
    const int arow = tid >> 1;            // 0..127
    const int asu  = (tid & 1) * 8;       // u32 offset
    const float* ap = A + (size_t)(bm + arow) * lda + asu * 2;
    // B staging: 4 threads/row, 8 floats each
    const int brow = tid >> 2;            // 0..63
    const int bsu  = (tid & 3) * 4;       // u32 offset
    const float* bp = B + (size_t)(bn + brow) * ldb + bsu * 2;

    float c[2][4][4];
#pragma unroll
    for (int mt = 0; mt < 2; ++mt)
#pragma unroll
        for (int nt = 0; nt < 4; ++nt)
#pragma unroll
            for (int i = 0; i < 4; ++i) c[mt][nt][i] = 0.0f;

    float4 pa[4], pb[2];
#pragma unroll
    for (int j = 0; j < 4; ++j) pa[j] = *(const float4*)(ap + j * 4);
#pragma unroll
    for (int j = 0; j < 2; ++j) pb[j] = *(const float4*)(bp + j * 4);

    for (int kt = 0; kt < kdim; kt += 32) {
#pragma unroll
        for (int j = 0; j < 4; ++j)
            cvt_store_hl(&Ah[arow * SK + asu + j * 2], &Al[arow * SK + asu + j * 2], pa[j]);
#pragma unroll
        for (int j = 0; j < 2; ++j)
            cvt_store_hl(&Bh[brow * SK + bsu + j * 2], &Bl[brow * SK + bsu + j * 2], pb[j]);
        __syncthreads();

        if (kt + 32 < kdim) {
#pragma unroll
            for (int j = 0; j < 4; ++j) pa[j] = *(const float4*)(ap + kt + 32 + j * 4);
#pragma unroll
            for (int j = 0; j < 2; ++j) pb[j] = *(const float4*)(bp + kt + 32 + j * 4);
        }

#pragma unroll
        for (int k16 = 0; k16 < 2; ++k16) {
            const int kb = k16 * 8 + tg;
            uint32_t ah[2][4], al[2][4], bh[4][2], bl[4][2];
#pragma unroll
            for (int mt = 0; mt < 2; ++mt) {
                const int r = (wm * 32 + mt * 16 + g) * SK + kb;
                ah[mt][0] = Ah[r];     ah[mt][1] = Ah[r + 8 * SK];
                ah[mt][2] = Ah[r + 4]; ah[mt][3] = Ah[r + 8 * SK + 4];
                al[mt][0] = Al[r];     al[mt][1] = Al[r + 8 * SK];
                al[mt][2] = Al[r + 4]; al[mt][3] = Al[r + 8 * SK + 4];
            }
#pragma unroll
            for (int nt = 0; nt < 4; ++nt) {
                const int r = (wn * 32 + nt * 8 + g) * SK + kb;
                bh[nt][0] = Bh[r];  bh[nt][1] = Bh[r + 4];
                bl[nt][0] = Bl[r];  bl[nt][1] = Bl[r + 4];
            }
#pragma unroll
            for (int mt = 0; mt < 2; ++mt)
#pragma unroll
                for (int nt = 0; nt < 4; ++nt) {
                    mma16816(c[mt][nt], ah[mt], bh[nt]);
                    mma16816(c[mt][nt], ah[mt], bl[nt]);
                    mma16816(c[mt][nt], al[mt], bh[nt]);
                }
        }
        __syncthreads();
    }

    // epilogue
#pragma unroll
    for (int mt = 0; mt < 2; ++mt) {
#pragma unroll
        for (int nt = 0; nt < 4; ++nt) {
            const int r0 = bm + wm * 32 + mt * 16 + g;
            const int n0 = bn + wn * 32 + nt * 8 + tg * 2;
            float2 v0 = make_float2(c[mt][nt][0], c[mt][nt][1]);
            float2 v1 = make_float2(c[mt][nt][2], c[mt][nt][3]);
            if (mode == 2) {
                v0.x *= scale; v0.y *= scale;
                v1.x *= scale; v1.y *= scale;
                *(float2*)(C + (size_t)r0 * ldc + n0)       = v0;
                *(float2*)(C + (size_t)(r0 + 8) * ldc + n0) = v1;
            } else {
                const float2 bb = *(const float2*)&bias[n0];
                v0.x += bb.x; v0.y += bb.y;
                v1.x += bb.x; v1.y += bb.y;
                if (mode == 1) {
                    const int h = n0 >> 6, d = n0 & 63;
                    const int b0 = r0 >> 11, s0 = r0 & 2047;
                    const int b1 = (r0 + 8) >> 11, s1 = (r0 + 8) & 2047;
                    *(float2*)(C + ((size_t)(b0 * HEADS + h) * SEQ + s0) * HDIM + d) = v0;
                    *(float2*)(C + ((size_t)(b1 * HEADS + h) * SEQ + s1) * HDIM + d) = v1;
                } else {
                    *(float2*)(C + (size_t)r0 * ldc + n0)       = v0;
                    *(float2*)(C + (size_t)(r0 + 8) * ldc + n0) = v1;
                }
            }
        }
    }
}

// Generic wrapper with z-strides (scores + O projection)
__global__ __launch_bounds__(256, 2) void gemm_bf16s_kernel(
    const float* __restrict__ Ag, const float* __restrict__ Bg,
    const float* __restrict__ bias, float* __restrict__ Cg,
    int lda, int ldb, int ldc, int kdim,
    size_t sAz, size_t sBz, size_t sCz,
    int mode, float scale)
{
    const int z = blockIdx.z;
    gemm_core(Ag + (size_t)z * sAz, Bg + (size_t)z * sBz, bias,
              Cg + (size_t)z * sCz,
              lda, ldb, ldc, kdim, mode, scale,
              blockIdx.y * 128, blockIdx.x * 64);
}

// Fused Q/K/V projection: blockIdx.z selects which projection
__global__ __launch_bounds__(256, 2) void qkv_proj_kernel(
    const float* __restrict__ q, const float* __restrict__ k,
    const float* __restrict__ v,
    const float* __restrict__ qw, const float* __restrict__ kw,
    const float* __restrict__ vw,
    const float* __restrict__ qb, const float* __restrict__ kb,
    const float* __restrict__ vb,
    float* __restrict__ dQ, float* __restrict__ dK, float* __restrict__ dV)
{
    const int z = blockIdx.z;
    const float* A = (z == 0) ? q : (z == 1) ? k : v;
    const float* W = (z == 0) ? qw : (z == 1) ? kw : vw;
    const float* B = (z == 0) ? qb : (z == 1) ? kb : vb;
    float* D = (z == 0) ? dQ : (z == 1) ? dK : dV;
    gemm_core(A, W, B, D, EMBED, EMBED, 0, EMBED, 1, 1.0f,
              blockIdx.y * 128, blockIdx.x * 64);
}

// ===========================================================================
// av: AO[z][q][d] = sum_k attn[z][q][k] * V[z][k][d]
// CTA tile 128(q) x 64(d), BK=32, 8 warps as 4m x 2n, warp tile 32x32.
// ===========================================================================
__global__ __launch_bounds__(256, 2) void av_mma_kernel(
    const float* __restrict__ attn, const float* __restrict__ Vg,
    float* __restrict__ ao)
{
    __shared__ uint32_t Ah[128 * SK], Al[128 * SK], Bh[64 * SK], Bl[64 * SK];

    const int tid = threadIdx.x;
    const int w   = tid >> 5;
    const int lid = tid & 31;
    const int g   = lid >> 2;
    const int tg  = lid & 3;
    const int wm  = w >> 1;        // 0..3
    const int wn  = w & 1;         // 0..1

    const int z  = blockIdx.y;
    const int bm = blockIdx.x * 128;

    const float* Wp = attn + (size_t)z * SEQ * SEQ + (size_t)bm * SEQ;
    const float* Vp = Vg + (size_t)z * SEQ * HDIM;

    const int srow = tid >> 1;
    const int su   = (tid & 1) * 8;
    const float* ap = Wp + (size_t)srow * SEQ + su * 2;

    const int vn  = tid & 63;      // d index
    const int kp0 = tid >> 6;      // 0..3

    float c[2][4][4];
#pragma unroll
    for (int mt = 0; mt < 2; ++mt)
#pragma unroll
        for (int nt = 0; nt < 4; ++nt)
#pragma unroll
            for (int i = 0; i < 4; ++i) c[mt][nt][i] = 0.0f;

    float4 pa[4];
    float  pv[8];
#pragma unroll
    for (int j = 0; j < 4; ++j) pa[j] = *(const float4*)(ap + j * 4);
#pragma unroll
    for (int p = 0; p < 4; ++p) {
        const int kp = p * 4 + kp0;
        pv[p * 2]     = Vp[(size_t)(kp * 2) * HDIM + vn];
        pv[p * 2 + 1] = Vp[(size_t)(kp * 2 + 1) * HDIM + vn];
    }

    for (int kt = 0; kt < SEQ; kt += 32) {
#pragma unroll
        for (int j = 0; j < 4; ++j)
            cvt_store_hl(&Ah[srow * SK + su + j * 2], &Al[srow * SK + su + j * 2], pa[j]);
#pragma unroll
        for (int p = 0; p < 4; ++p) {
            const int kp = p * 4 + kp0;
            const float v0 = pv[p * 2], v1 = pv[p * 2 + 1];
            __nv_bfloat16 h0 = __float2bfloat16(v0);
            __nv_bfloat16 h1 = __float2bfloat16(v1);
            Bh[vn * SK + kp] = pack_bf16x2(h0, h1);
            Bl[vn * SK + kp] = pack_bf16x2(
                __float2bfloat16(v0 - __bfloat162float(h0)),
                __float2bfloat16(v1 - __bfloat162float(h1)));
        }
        __syncthreads();

        if (kt + 32 < SEQ) {
#pragma unroll
            for (int j = 0; j < 4; ++j)
                pa[j] = *(const float4*)(ap + kt + 32 + j * 4);
#pragma unroll
            for (int p = 0; p < 4; ++p) {
                const int kp = p * 4 + kp0;
                pv[p * 2]     = Vp[(size_t)(kt + 32 + kp * 2) * HDIM + vn];
                pv[p * 2 + 1] = Vp[(size_t)(kt + 32 + kp * 2 + 1) * HDIM + vn];
            }
        }

#pragma unroll
        for (int k16 = 0; k16 < 2; ++k16) {
            const int kb = k16 * 8 + tg;
            uint32_t ah[2][4], al[2][4], bh[4][2], bl[4][2];
#pragma unroll
            for (int mt = 0; mt < 2; ++mt) {
                const int r = (wm * 32 + mt * 16 + g) * SK + kb;
                ah[mt][0] = Ah[r];     ah[mt][1] = Ah[r + 8 * SK];
                ah[mt][2] = Ah[r + 4]; ah[mt][3] = Ah[r + 8 * SK + 4];
                al[mt][0] = Al[r];     al[mt][1] = Al[r + 8 * SK];
                al[mt][2] = Al[r + 4]; al[mt][3] = Al[r + 8 * SK + 4];
            }
#pragma unroll
            for (int nt = 0; nt < 4; ++nt) {
                const int r = (wn * 32 + nt * 8 + g) * SK + kb;
                bh[nt][0] = Bh[r];  bh[nt][1] = Bh[r + 4];
                bl[nt][0] = Bl[r];  bl[nt][1] = Bl[r + 4];
            }
#pragma unroll
            for (int mt = 0; mt < 2; ++mt)
#pragma unroll
                for (int nt = 0; nt < 4; ++nt) {
                    mma16816(c[mt][nt], ah[mt], bh[nt]);
                    mma16816(c[mt][nt], ah[mt], bl[nt]);
                    mma16816(c[mt][nt], al[mt], bh[nt]);
                }
        }
        __syncthreads();
    }

    const int b = z >> 4, h = z & 15;
#pragma unroll
    for (int mt = 0; mt < 2; ++mt) {
#pragma unroll
        for (int nt = 0; nt < 4; ++nt) {
            const int q0 = bm + wm * 32 + mt * 16 + g;
            const int d0 = wn * 32 + nt * 8 + tg * 2;
            float* p0 = ao + ((size_t)(b * SEQ + q0)) * EMBED + h * HDIM + d0;
            float* p1 = ao + ((size_t)(b * SEQ + q0 + 8)) * EMBED + h * HDIM + d0;
            *(float2*)p0 = make_float2(c[mt][nt][0], c[mt][nt][1]);
            *(float2*)p1 = make_float2(c[mt][nt][2], c[mt][nt][3]);
        }
    }
}

// ---------------------------------------------------------------------------
// Softmax: in-place over rows of 2048. One CTA (256 thr) per row.
// ---------------------------------------------------------------------------
__global__ __launch_bounds__(256) void softmax_kernel(float* __restrict__ attn)
{
    const size_t row = blockIdx.x;
    float* p = attn + row * SEQ;
    const int t = threadIdx.x;

    float x[8];
    *(float4*)(x)     = ((const float4*)p)[2 * t];
    *(float4*)(x + 4) = ((const float4*)p)[2 * t + 1];

    __shared__ float sred[8];
    const int lane = t & 31;
    const int wid  = t >> 5;

    float m = x[0];
#pragma unroll
    for (int i = 1; i < 8; ++i) m = fmaxf(m, x[i]);
#pragma unroll
    for (int o = 16; o > 0; o >>= 1)
        m = fmaxf(m, __shfl_xor_sync(0xffffffffu, m, o));
    if (lane == 0) sred[wid] = m;
    __syncthreads();
    m = sred[0];
#pragma unroll
    for (int w = 1; w < 8; ++w) m = fmaxf(m, sred[w]);
    __syncthreads();

    float s = 0.0f;
#pragma unroll
    for (int i = 0; i < 8; ++i) {
        x[i] = __expf(x[i] - m);
        s += x[i];
    }
#pragma unroll
    for (int o = 16; o > 0; o >>= 1)
        s += __shfl_xor_sync(0xffffffffu, s, o);
    if (lane == 0) sred[wid] = s;
    __syncthreads();
    s = 0.0f;
#pragma unroll
    for (int w = 0; w < 8; ++w) s += sred[w];

    const float inv = 1.0f / s;
#pragma unroll
    for (int i = 0; i < 8; ++i) x[i] *= inv;
    ((float4*)p)[2 * t]     = *(float4*)(x);
    ((float4*)p)[2 * t + 1] = *(float4*)(x + 4);
}

// ---------------------------------------------------------------------------
// launch
// ---------------------------------------------------------------------------
extern "C" void kernel_launch(void* const* d_in, const int* in_sizes, int n_in,
                              void* d_out, int out_size)
{
    (void)in_sizes; (void)n_in; (void)out_size;
    const float* query = (const float*)d_in[0];
    const float* key   = (const float*)d_in[1];
    const float* value = (const float*)d_in[2];
    const float* q_w   = (const float*)d_in[3];
    const float* q_b   = (const float*)d_in[4];
    const float* k_w   = (const float*)d_in[5];
    const float* k_b   = (const float*)d_in[6];
    const float* v_w   = (const float*)d_in[7];
    const float* v_b   = (const float*)d_in[8];
    const float* o_w   = (const float*)d_in[9];
    const float* o_b   = (const float*)d_in[10];

    float* out  = (float*)d_out;                 // [B,S,E]
    float* attn = out + OUT_ELEMS;               // [B,H,S,S]

    float *pQ, *pK, *pV, *pAO;
    cudaGetSymbolAddress((void**)&pQ, g_Q);
    cudaGetSymbolAddress((void**)&pK, g_K);
    cudaGetSymbolAddress((void**)&pV, g_V);
    cudaGetSymbolAddress((void**)&pAO, g_AO);

    // 1) fused Q/K/V projections (mode 1, split-head stores)
    dim3 qkvgrid(EMBED / 64, MTOT / 128, 3);     // (16, 32, 3)
    qkv_proj_kernel<<<qkvgrid, 256>>>(query, key, value,
                                      q_w, k_w, v_w, q_b, k_b, v_b,
                                      pQ, pK, pV);

    // 2) scores: attn[z] = (Q_z @ K_z^T) * 0.125 (mode 2)
    dim3 sgrid(SEQ / 64, SEQ / 128, BATCH * HEADS);  // (32, 16, 32)
    gemm_bf16s_kernel<<<sgrid, 256>>>(pQ, pK, nullptr, attn,
                                      HDIM, HDIM, SEQ, HDIM,
                                      (size_t)SEQ * HDIM, (size_t)SEQ * HDIM,
                                      (size_t)SEQ * SEQ, 2, 0.125f);

    // 3) softmax in place
    softmax_kernel<<<(unsigned)(BATCH * HEADS * SEQ), 256>>>(attn);

    // 4) attn @ V -> merged heads
    dim3 avgrid(SEQ / 128, BATCH * HEADS);       // (16, 32)
    av_mma_kernel<<<avgrid, 256>>>(attn, pV, pAO);

    // 5) output projection (mode 0)
    dim3 ogrid(EMBED / 64, MTOT / 128, 1);       // (16, 32)
    gemm_bf16s_kernel<<<ogrid, 256>>>(pAO, o_w, o_b, out,
                                      EMBED, EMBED, EMBED, EMBED, 0, 0, 0, 0, 1.0f);
}

// round 11
// speedup vs baseline: 1.0581x; 1.0581x over previous
#include <cuda_runtime.h>
#include <cuda_bf16.h>
#include <cstdint>
#include <cstddef>

// Problem constants
#define BATCH   2
#define SEQ     2048
#define EMBED   1024
#define HEADS   16
#define HDIM    64
#define MTOT    (BATCH * SEQ)          // 4096
#define OUT_ELEMS   ((size_t)BATCH * SEQ * EMBED)                    // 4,194,304

// Scratch
__device__ float g_Q[BATCH * HEADS * SEQ * HDIM];
__device__ float g_K[BATCH * HEADS * SEQ * HDIM];
__device__ float g_V[BATCH * HEADS * SEQ * HDIM];
__device__ float g_AO[BATCH * SEQ * EMBED];
// partial row sums of exp(scores): [z][q][32 k-blocks]
__device__ float g_psum[(size_t)BATCH * HEADS * SEQ * 32];

// ===========================================================================
// helpers
// ===========================================================================
__device__ __forceinline__ uint32_t pack_bf16x2(__nv_bfloat16 a, __nv_bfloat16 b) {
    __nv_bfloat162 t;
    t.x = a; t.y = b;
    return *reinterpret_cast<uint32_t*>(&t);
}

// hi/lo split of a float4 -> two u32 each (pairs along k)
__device__ __forceinline__ void cvt_store_hl(uint32_t* hi, uint32_t* lo, float4 v) {
    __nv_bfloat16 hx = __float2bfloat16(v.x);
    __nv_bfloat16 hy = __float2bfloat16(v.y);
    __nv_bfloat16 hz = __float2bfloat16(v.z);
    __nv_bfloat16 hw = __float2bfloat16(v.w);
    hi[0] = pack_bf16x2(hx, hy);
    hi[1] = pack_bf16x2(hz, hw);
    lo[0] = pack_bf16x2(__float2bfloat16(v.x - __bfloat162float(hx)),
                        __float2bfloat16(v.y - __bfloat162float(hy)));
    lo[1] = pack_bf16x2(__float2bfloat16(v.z - __bfloat162float(hz)),
                        __float2bfloat16(v.w - __bfloat162float(hw)));
}

// mma.sync m16n8k16 bf16 -> f32, C += A*B
__device__ __forceinline__ void mma16816(float* c, const uint32_t* a, const uint32_t* b) {
    asm volatile(
        "mma.sync.aligned.m16n8k16.row.col.f32.bf16.bf16.f32 "
        "{%0,%1,%2,%3}, {%4,%5,%6,%7}, {%8,%9}, {%0,%1,%2,%3};\n"
        : "+f"(c[0]), "+f"(c[1]), "+f"(c[2]), "+f"(c[3])
        : "r"(a[0]), "r"(a[1]), "r"(a[2]), "r"(a[3]), "r"(b[0]), "r"(b[1]));
}

// smem row stride in u32 for BK=32 tiles: 16 data + 4 pad (conflict-free)
#define SK 20
// dynamic smem layout (u32 units): two stages of (Ah|Al|Bh|Bl), then extras
#define STAGE_U32 7680              // 128*SK*2 + 64*SK*2
#define EXTRA_OFF 15360             // after both stages
#define GEMM_SMEM ((EXTRA_OFF + 256) * 4)   // + spart[256]
#define AV_SMEM   ((EXTRA_OFF + 128) * 4)   // + s_inv[128]

// ===========================================================================
// Core split-bf16 GEMM tile: C[128, 64] = A[128, Kd] * B[64, Kd]^T
// 256 threads, 8 warps as 4m x 2n, warp tile 32x32.
// Double-buffered smem pipeline: 1 barrier per k-slab, STS overlaps MMA.
// mode 0: C[r*ldc+n] = acc + bias[n]
// mode 1: split-head store to [B,H,S,Dh], + bias[n]
// mode 3: C = exp(acc*scale) (unnormalized), write partial row sums to psum
// ===========================================================================
__device__ __forceinline__ void gemm_core(
    const float* __restrict__ A, const float* __restrict__ B,
    const float* __restrict__ bias, float* __restrict__ C,
    int lda, int ldb, int ldc, int kdim, int mode, float scale,
    int bm, int bn, float* __restrict__ psum, int kb)
{
    extern __shared__ uint32_t dsm[];

    const int tid = threadIdx.x;
    const int w   = tid >> 5;
    const int lid = tid & 31;
    const int g   = lid >> 2;      // 0..7
    const int tg  = lid & 3;       // 0..3
    const int wm  = w >> 1;        // 0..3
    const int wn  = w & 1;         // 0..1

    // A staging: 2 threads/row, 16 floats each
    const int arow = tid >> 1;            // 0..127
    const int asu  = (tid & 1) * 8;       // u32 offset
    const float* ap = A + (size_t)(bm + arow) * lda + asu * 2;
    // B staging: 4 threads/row, 8 floats each
    const int brow = tid >> 2;            // 0..63
    const int bsu  = (tid & 3) * 4;       // u32 offset
    const float* bp = B + (size_t)(bn + brow) * ldb + bsu * 2;

    float c[2][4][4];
#pragma unroll
    for (int mt = 0; mt < 2; ++mt)
#pragma unroll
        for (int nt = 0; nt < 4; ++nt)
#pragma unroll
            for (int i = 0; i < 4; ++i) c[mt][nt][i] = 0.0f;

    float4 pa[4], pb[2];
#pragma unroll
    for (int j = 0; j < 4; ++j) pa[j] = *(const float4*)(ap + j * 4);
#pragma unroll
    for (int j = 0; j < 2; ++j) pb[j] = *(const float4*)(bp + j * 4);

    // stage 0 fill
    {
        uint32_t* Ah = dsm;
        uint32_t* Al = dsm + 2560;
        uint32_t* Bh = dsm + 5120;
        uint32_t* Bl = dsm + 6400;
#pragma unroll
        for (int j = 0; j < 4; ++j)
            cvt_store_hl(&Ah[arow * SK + asu + j * 2], &Al[arow * SK + asu + j * 2], pa[j]);
#pragma unroll
        for (int j = 0; j < 2; ++j)
            cvt_store_hl(&Bh[brow * SK + bsu + j * 2], &Bl[brow * SK + bsu + j * 2], pb[j]);
    }
    __syncthreads();

    int stage = 0;
#pragma unroll 1
    for (int kt = 0; kt < kdim; kt += 32) {
        const bool nx = (kt + 32 < kdim);
        if (nx) {
#pragma unroll
            for (int j = 0; j < 4; ++j) pa[j] = *(const float4*)(ap + kt + 32 + j * 4);
#pragma unroll
            for (int j = 0; j < 2; ++j) pb[j] = *(const float4*)(bp + kt + 32 + j * 4);
        }

        uint32_t* base = dsm + stage * STAGE_U32;
        uint32_t* Ah = base;
        uint32_t* Al = base + 2560;
        uint32_t* Bh = base + 5120;
        uint32_t* Bl = base + 6400;

#pragma unroll
        for (int k16 = 0; k16 < 2; ++k16) {
            const int kbk = k16 * 8 + tg;
            uint32_t ah[2][4], al[2][4], bh[4][2], bl[4][2];
#pragma unroll
            for (int mt = 0; mt < 2; ++mt) {
                const int r = (wm * 32 + mt * 16 + g) * SK + kbk;
                ah[mt][0] = Ah[r];     ah[mt][1] = Ah[r + 8 * SK];
                ah[mt][2] = Ah[r + 4]; ah[mt][3] = Ah[r + 8 * SK + 4];
                al[mt][0] = Al[r];     al[mt][1] = Al[r + 8 * SK];
                al[mt][2] = Al[r + 4]; al[mt][3] = Al[r + 8 * SK + 4];
            }
#pragma unroll
            for (int nt = 0; nt < 4; ++nt) {
                const int r = (wn * 32 + nt * 8 + g) * SK + kbk;
                bh[nt][0] = Bh[r];  bh[nt][1] = Bh[r + 4];
                bl[nt][0] = Bl[r];  bl[nt][1] = Bl[r + 4];
            }
#pragma unroll
            for (int mt = 0; mt < 2; ++mt)
#pragma unroll
                for (int nt = 0; nt < 4; ++nt) {
                    mma16816(c[mt][nt], ah[mt], bh[nt]);
                    mma16816(c[mt][nt], ah[mt], bl[nt]);
                    mma16816(c[mt][nt], al[mt], bh[nt]);
                }
        }

        if (nx) {
            uint32_t* nb  = dsm + (stage ^ 1) * STAGE_U32;
            uint32_t* nAh = nb;
            uint32_t* nAl = nb + 2560;
            uint32_t* nBh = nb + 5120;
            uint32_t* nBl = nb + 6400;
#pragma unroll
            for (int j = 0; j < 4; ++j)
                cvt_store_hl(&nAh[arow * SK + asu + j * 2], &nAl[arow * SK + asu + j * 2], pa[j]);
#pragma unroll
            for (int j = 0; j < 2; ++j)
                cvt_store_hl(&nBh[brow * SK + bsu + j * 2], &nBl[brow * SK + bsu + j * 2], pb[j]);
        }
        __syncthreads();
        stage ^= 1;
    }

    // epilogue
    if (mode == 3) {
        float rs0[2], rs1[2];
        rs0[0] = rs0[1] = rs1[0] = rs1[1] = 0.0f;
#pragma unroll
        for (int mt = 0; mt < 2; ++mt) {
#pragma unroll
            for (int nt = 0; nt < 4; ++nt) {
                const int r0 = bm + wm * 32 + mt * 16 + g;
                const int n0 = bn + wn * 32 + nt * 8 + tg * 2;
                float e0 = __expf(c[mt][nt][0] * scale);
                float e1 = __expf(c[mt][nt][1] * scale);
                float e2 = __expf(c[mt][nt][2] * scale);
                float e3 = __expf(c[mt][nt][3] * scale);
                *(float2*)(C + (size_t)r0 * ldc + n0)       = make_float2(e0, e1);
                *(float2*)(C + (size_t)(r0 + 8) * ldc + n0) = make_float2(e2, e3);
                rs0[mt] += e0 + e1;
                rs1[mt] += e2 + e3;
            }
        }
        // reduce over the 4 tg lanes (same rows)
#pragma unroll
        for (int o = 1; o <= 2; o <<= 1) {
            rs0[0] += __shfl_xor_sync(0xffffffffu, rs0[0], o);
            rs0[1] += __shfl_xor_sync(0xffffffffu, rs0[1], o);
            rs1[0] += __shfl_xor_sync(0xffffffffu, rs1[0], o);
            rs1[1] += __shfl_xor_sync(0xffffffffu, rs1[1], o);
        }
        float* spart = (float*)(dsm + EXTRA_OFF);   // [128][2]
        if (tg == 0) {
#pragma unroll
            for (int mt = 0; mt < 2; ++mt) {
                spart[(wm * 32 + mt * 16 + g) * 2 + wn]     = rs0[mt];
                spart[(wm * 32 + mt * 16 + g + 8) * 2 + wn] = rs1[mt];
            }
        }
        __syncthreads();
        if (tid < 128)
            psum[(size_t)(bm + tid) * 32 + kb] = spart[tid * 2] + spart[tid * 2 + 1];
    } else {
#pragma unroll
        for (int mt = 0; mt < 2; ++mt) {
#pragma unroll
            for (int nt = 0; nt < 4; ++nt) {
                const int r0 = bm + wm * 32 + mt * 16 + g;
                const int n0 = bn + wn * 32 + nt * 8 + tg * 2;
                const float2 bb = *(const float2*)&bias[n0];
                float2 v0 = make_float2(c[mt][nt][0] + bb.x, c[mt][nt][1] + bb.y);
                float2 v1 = make_float2(c[mt][nt][2] + bb.x, c[mt][nt][3] + bb.y);
                if (mode == 1) {
                    const int h = n0 >> 6, d = n0 & 63;
                    const int b0 = r0 >> 11, s0 = r0 & 2047;
                    const int b1 = (r0 + 8) >> 11, s1 = (r0 + 8) & 2047;
                    *(float2*)(C + ((size_t)(b0 * HEADS + h) * SEQ + s0) * HDIM + d) = v0;
                    *(float2*)(C + ((size_t)(b1 * HEADS + h) * SEQ + s1) * HDIM + d) = v1;
                } else {
                    *(float2*)(C + (size_t)r0 * ldc + n0)       = v0;
                    *(float2*)(C + (size_t)(r0 + 8) * ldc + n0) = v1;
                }
            }
        }
    }
}

// Generic wrapper with z-strides (scores + O projection)
__global__ __launch_bounds__(256, 1) void gemm_bf16s_kernel(
    const float* __restrict__ Ag, const float* __restrict__ Bg,
    const float* __restrict__ bias, float* __restrict__ Cg,
    int lda, int ldb, int ldc, int kdim,
    size_t sAz, size_t sBz, size_t sCz,
    int mode, float scale, float* __restrict__ psum)
{
    const int z = blockIdx.z;
    float* pz = psum ? (psum + (size_t)z * SEQ * 32) : nullptr;
    gemm_core(Ag + (size_t)z * sAz, Bg + (size_t)z * sBz, bias,
              Cg + (size_t)z * sCz,
              lda, ldb, ldc, kdim, mode, scale,
              blockIdx.y * 128, blockIdx.x * 64, pz, blockIdx.x);
}

// Fused Q/K/V projection: blockIdx.z selects which projection
__global__ __launch_bounds__(256, 1) void qkv_proj_kernel(
    const float* __restrict__ q, const float* __restrict__ k,
    const float* __restrict__ v,
    const float* __restrict__ qw, const float* __restrict__ kw,
    const float* __restrict__ vw,
    const float* __restrict__ qb, const float* __restrict__ kb,
    const float* __restrict__ vb,
    float* __restrict__ dQ, float* __restrict__ dK, float* __restrict__ dV)
{
    const int z = blockIdx.z;
    const float* A = (z == 0) ? q : (z == 1) ? k : v;
    const float* W = (z == 0) ? qw : (z == 1) ? kw : vw;
    const float* B = (z == 0) ? qb : (z == 1) ? kb : vb;
    float* D = (z == 0) ? dQ : (z == 1) ? dK : dV;
    gemm_core(A, W, B, D, EMBED, EMBED, 0, EMBED, 1, 1.0f,
              blockIdx.y * 128, blockIdx.x * 64, nullptr, 0);
}

// ===========================================================================
// av: reads unnormalized exp scores, normalizes (writes back normalized
// attn weights in place), computes AO = P_norm @ V with split-bf16 MMA.
// CTA tile 128(q) x 64(d), BK=32, double-buffered pipeline.
// ===========================================================================
__global__ __launch_bounds__(256, 1) void av_mma_kernel(
    float* __restrict__ attn, const float* __restrict__ Vg,
    const float* __restrict__ psum, float* __restrict__ ao)
{
    extern __shared__ uint32_t dsm[];
    float* s_inv = (float*)(dsm + EXTRA_OFF);   // [128]

    const int tid = threadIdx.x;
    const int w   = tid >> 5;
    const int lid = tid & 31;
    const int g   = lid >> 2;
    const int tg  = lid & 3;
    const int wm  = w >> 1;        // 0..3
    const int wn  = w & 1;         // 0..1

    const int z  = blockIdx.y;
    const int bm = blockIdx.x * 128;

    float* Wp = attn + (size_t)z * SEQ * SEQ + (size_t)bm * SEQ;
    const float* Vp = Vg + (size_t)z * SEQ * HDIM;

    // row inverse sums (deterministic reduction of 32 partials)
    if (tid < 128) {
        const float* pp = psum + ((size_t)z * SEQ + bm + tid) * 32;
        float s = 0.0f;
#pragma unroll
        for (int i = 0; i < 32; ++i) s += pp[i];
        s_inv[tid] = 1.0f / s;
    }
    __syncthreads();

    const int arow = tid >> 1;
    const int asu  = (tid & 1) * 8;
    float* apw = Wp + (size_t)arow * SEQ + asu * 2;
    const float inv = s_inv[arow];

    const int vn  = tid & 63;      // d index
    const int kp0 = tid >> 6;      // 0..3

    float c[2][4][4];
#pragma unroll
    for (int mt = 0; mt < 2; ++mt)
#pragma unroll
        for (int nt = 0; nt < 4; ++nt)
#pragma unroll
            for (int i = 0; i < 4; ++i) c[mt][nt][i] = 0.0f;

    float4 pa[4];
    float  pv[8];
#pragma unroll
    for (int j = 0; j < 4; ++j) pa[j] = *(const float4*)(apw + j * 4);
#pragma unroll
    for (int p = 0; p < 4; ++p) {
        const int kp = p * 4 + kp0;
        pv[p * 2]     = Vp[(size_t)(kp * 2) * HDIM + vn];
        pv[p * 2 + 1] = Vp[(size_t)(kp * 2 + 1) * HDIM + vn];
    }

    // normalize + write-back + stage helper
    auto stage_tiles = [&](uint32_t* base, float* wb_ptr) {
        uint32_t* Ah = base;
        uint32_t* Al = base + 2560;
#pragma unroll
        for (int j = 0; j < 4; ++j) {
            float4 vv = make_float4(pa[j].x * inv, pa[j].y * inv,
                                    pa[j].z * inv, pa[j].w * inv);
            *(float4*)(wb_ptr + j * 4) = vv;   // normalized attn weights
            cvt_store_hl(&Ah[arow * SK + asu + j * 2], &Al[arow * SK + asu + j * 2], vv);
        }
        uint32_t* Bh = base + 5120;
        uint32_t* Bl = base + 6400;
#pragma unroll
        for (int p = 0; p < 4; ++p) {
            const int kp = p * 4 + kp0;
            const float v0 = pv[p * 2], v1 = pv[p * 2 + 1];
            __nv_bfloat16 h0 = __float2bfloat16(v0);
            __nv_bfloat16 h1 = __float2bfloat16(v1);
            Bh[vn * SK + kp] = pack_bf16x2(h0, h1);
            Bl[vn * SK + kp] = pack_bf16x2(
                __float2bfloat16(v0 - __bfloat162float(h0)),
                __float2bfloat16(v1 - __bfloat162float(h1)));
        }
    };

    stage_tiles(dsm, apw);
    __syncthreads();

    int stage = 0;
#pragma unroll 1
    for (int kt = 0; kt < SEQ; kt += 32) {
        const bool nx = (kt + 32 < SEQ);
        if (nx) {
#pragma unroll
            for (int j = 0; j < 4; ++j)
                pa[j] = *(const float4*)(apw + kt + 32 + j * 4);
#pragma unroll
            for (int p = 0; p < 4; ++p) {
                const int kp = p * 4 + kp0;
                pv[p * 2]     = Vp[(size_t)(kt + 32 + kp * 2) * HDIM + vn];
                pv[p * 2 + 1] = Vp[(size_t)(kt + 32 + kp * 2 + 1) * HDIM + vn];
            }
        }

        uint32_t* base = dsm + stage * STAGE_U32;
        uint32_t* Ah = base;
        uint32_t* Al = base + 2560;
        uint32_t* Bh = base + 5120;
        uint32_t* Bl = base + 6400;

#pragma unroll
        for (int k16 = 0; k16 < 2; ++k16) {
            const int kbk = k16 * 8 + tg;
            uint32_t ah[2][4], al[2][4], bh[4][2], bl[4][2];
#pragma unroll
            for (int mt = 0; mt < 2; ++mt) {
                const int r = (wm * 32 + mt * 16 + g) * SK + kbk;
                ah[mt][0] = Ah[r];     ah[mt][1] = Ah[r + 8 * SK];
                ah[mt][2] = Ah[r + 4]; ah[mt][3] = Ah[r + 8 * SK + 4];
                al[mt][0] = Al[r];     al[mt][1] = Al[r + 8 * SK];
                al[mt][2] = Al[r + 4]; al[mt][3] = Al[r + 8 * SK + 4];
            }
#pragma unroll
            for (int nt = 0; nt < 4; ++nt) {
                const int r = (wn * 32 + nt * 8 + g) * SK + kbk;
                bh[nt][0] = Bh[r];  bh[nt][1] = Bh[r + 4];
                bl[nt][0] = Bl[r];  bl[nt][1] = Bl[r + 4];
            }
#pragma unroll
            for (int mt = 0; mt < 2; ++mt)
#pragma unroll
                for (int nt = 0; nt < 4; ++nt) {
                    mma16816(c[mt][nt], ah[mt], bh[nt]);
                    mma16816(c[mt][nt], ah[mt], bl[nt]);
                    mma16816(c[mt][nt], al[mt], bh[nt]);
                }
        }

        if (nx)
            stage_tiles(dsm + (stage ^ 1) * STAGE_U32, apw + kt + 32);
        __syncthreads();
        stage ^= 1;
    }

    const int b = z >> 4, h = z & 15;
#pragma unroll
    for (int mt = 0; mt < 2; ++mt) {
#pragma unroll
        for (int nt = 0; nt < 4; ++nt) {
            const int q0 = bm + wm * 32 + mt * 16 + g;
            const int d0 = wn * 32 + nt * 8 + tg * 2;
            float* p0 = ao + ((size_t)(b * SEQ + q0)) * EMBED + h * HDIM + d0;
            float* p1 = ao + ((size_t)(b * SEQ + q0 + 8)) * EMBED + h * HDIM + d0;
            *(float2*)p0 = make_float2(c[mt][nt][0], c[mt][nt][1]);
            *(float2*)p1 = make_float2(c[mt][nt][2], c[mt][nt][3]);
        }
    }
}

// ---------------------------------------------------------------------------
// launch
// ---------------------------------------------------------------------------
extern "C" void kernel_launch(void* const* d_in, const int* in_sizes, int n_in,
                              void* d_out, int out_size)
{
    (void)in_sizes; (void)n_in; (void)out_size;
    const float* query = (const float*)d_in[0];
    const float* key   = (const float*)d_in[1];
    const float* value = (const float*)d_in[2];
    const float* q_w   = (const float*)d_in[3];
    const float* q_b   = (const float*)d_in[4];
    const float* k_w   = (const float*)d_in[5];
    const float* k_b   = (const float*)d_in[6];
    const float* v_w   = (const float*)d_in[7];
    const float* v_b   = (const float*)d_in[8];
    const float* o_w   = (const float*)d_in[9];
    const float* o_b   = (const float*)d_in[10];

    float* out  = (float*)d_out;                 // [B,S,E]
    float* attn = out + OUT_ELEMS;               // [B,H,S,S]

    float *pQ, *pK, *pV, *pAO, *pPS;
    cudaGetSymbolAddress((void**)&pQ, g_Q);
    cudaGetSymbolAddress((void**)&pK, g_K);
    cudaGetSymbolAddress((void**)&pV, g_V);
    cudaGetSymbolAddress((void**)&pAO, g_AO);
    cudaGetSymbolAddress((void**)&pPS, g_psum);

    static bool attr_done = false;
    if (!attr_done) {
        cudaFuncSetAttribute(qkv_proj_kernel,
                             cudaFuncAttributeMaxDynamicSharedMemorySize, GEMM_SMEM);
        cudaFuncSetAttribute(gemm_bf16s_kernel,
                             cudaFuncAttributeMaxDynamicSharedMemorySize, GEMM_SMEM);
        cudaFuncSetAttribute(av_mma_kernel,
                             cudaFuncAttributeMaxDynamicSharedMemorySize, AV_SMEM);
        attr_done = true;
    }

    // 1) fused Q/K/V projections (mode 1, split-head stores)
    dim3 qkvgrid(EMBED / 64, MTOT / 128, 3);     // (16, 32, 3)
    qkv_proj_kernel<<<qkvgrid, 256, GEMM_SMEM>>>(query, key, value,
                                                 q_w, k_w, v_w, q_b, k_b, v_b,
                                                 pQ, pK, pV);

    // 2) scores: attn[z] = exp((Q_z @ K_z^T) * 0.125) unnormalized + psum
    dim3 sgrid(SEQ / 64, SEQ / 128, BATCH * HEADS);  // (32, 16, 32)
    gemm_bf16s_kernel<<<sgrid, 256, GEMM_SMEM>>>(pQ, pK, nullptr, attn,
                                                 HDIM, HDIM, SEQ, HDIM,
                                                 (size_t)SEQ * HDIM, (size_t)SEQ * HDIM,
                                                 (size_t)SEQ * SEQ, 3, 0.125f, pPS);

    // 3) av: normalize attn in place + AO = P @ V
    dim3 avgrid(SEQ / 128, BATCH * HEADS);       // (16, 32)
    av_mma_kernel<<<avgrid, 256, AV_SMEM>>>(attn, pV, pPS, pAO);

    // 4) output projection (mode 0)
    dim3 ogrid(EMBED / 64, MTOT / 128, 1);       // (16, 32)
    gemm_bf16s_kernel<<<ogrid, 256, GEMM_SMEM>>>(pAO, o_w, o_b, out,
                                                 EMBED, EMBED, EMBED, EMBED, 0, 0, 0,
                                                 0, 1.0f, nullptr);
}

// round 12
// speedup vs baseline: 1.1742x; 1.1097x over previous
#include <cuda_runtime.h>
#include <cuda_bf16.h>
#include <cstdint>
#include <cstddef>

// Problem constants
#define BATCH   2
#define SEQ     2048
#define EMBED   1024
#define HEADS   16
#define HDIM    64
#define MTOT    (BATCH * SEQ)          // 4096
#define OUT_ELEMS   ((size_t)BATCH * SEQ * EMBED)                    // 4,194,304

// Scratch
__device__ float g_Q[BATCH * HEADS * SEQ * HDIM];
__device__ float g_K[BATCH * HEADS * SEQ * HDIM];
__device__ float g_V[BATCH * HEADS * SEQ * HDIM];
__device__ float g_AO[BATCH * SEQ * EMBED];
// partial row sums of exp(scores): [z][q][32 k-blocks]
__device__ float g_psum[(size_t)BATCH * HEADS * SEQ * 32];

// ===========================================================================
// helpers
// ===========================================================================
__device__ __forceinline__ uint32_t pack_bf16x2(__nv_bfloat16 a, __nv_bfloat16 b) {
    __nv_bfloat162 t;
    t.x = a; t.y = b;
    return *reinterpret_cast<uint32_t*>(&t);
}

// hi/lo split of a float4 -> two u32 each (pairs along k)
__device__ __forceinline__ void cvt_store_hl(uint32_t* hi, uint32_t* lo, float4 v) {
    __nv_bfloat16 hx = __float2bfloat16(v.x);
    __nv_bfloat16 hy = __float2bfloat16(v.y);
    __nv_bfloat16 hz = __float2bfloat16(v.z);
    __nv_bfloat16 hw = __float2bfloat16(v.w);
    hi[0] = pack_bf16x2(hx, hy);
    hi[1] = pack_bf16x2(hz, hw);
    lo[0] = pack_bf16x2(__float2bfloat16(v.x - __bfloat162float(hx)),
                        __float2bfloat16(v.y - __bfloat162float(hy)));
    lo[1] = pack_bf16x2(__float2bfloat16(v.z - __bfloat162float(hz)),
                        __float2bfloat16(v.w - __bfloat162float(hw)));
}

// mma.sync m16n8k16 bf16 -> f32, C += A*B
__device__ __forceinline__ void mma16816(float* c, const uint32_t* a, const uint32_t* b) {
    asm volatile(
        "mma.sync.aligned.m16n8k16.row.col.f32.bf16.bf16.f32 "
        "{%0,%1,%2,%3}, {%4,%5,%6,%7}, {%8,%9}, {%0,%1,%2,%3};\n"
        : "+f"(c[0]), "+f"(c[1]), "+f"(c[2]), "+f"(c[3])
        : "r"(a[0]), "r"(a[1]), "r"(a[2]), "r"(a[3]), "r"(b[0]), "r"(b[1]));
}

// ldmatrix x4 (non-transposed)
__device__ __forceinline__ void ldsm4(uint32_t* r, uint32_t saddr) {
    asm volatile("ldmatrix.sync.aligned.m8n8.x4.shared.b16 {%0,%1,%2,%3}, [%4];"
                 : "=r"(r[0]), "=r"(r[1]), "=r"(r[2]), "=r"(r[3]) : "r"(saddr));
}

// smem row stride in u32 for BK=32 tiles: 16 data + 4 pad (conflict-free)
#define SK 20
// dynamic smem layout (u32 units): two stages of (Ah|Al|Bh|Bl), then extras
#define STAGE_U32 7680              // 128*SK*2 + 64*SK*2
#define EXTRA_OFF 15360             // after both stages
#define GEMM_SMEM ((EXTRA_OFF + 256) * 4)   // + spart[256]
#define AV_SMEM   ((EXTRA_OFF + 128) * 4)   // + s_inv[128]

// ===========================================================================
// Core split-bf16 GEMM tile: C[128, 64] = A[128, Kd] * B[64, Kd]^T
// 256 threads, 8 warps as 4m x 2n, warp tile 32x32.
// Double-buffered smem pipeline, ldmatrix fragment loads, pass-reordered MMAs.
// mode 0: C[r*ldc+n] = acc + bias[n]
// mode 1: split-head store to [B,H,S,Dh], + bias[n]
// mode 3: C = exp(acc*scale) (unnormalized), write partial row sums to psum
// ===========================================================================
__device__ __forceinline__ void gemm_core(
    const float* __restrict__ A, const float* __restrict__ B,
    const float* __restrict__ bias, float* __restrict__ C,
    int lda, int ldb, int ldc, int kdim, int mode, float scale,
    int bm, int bn, float* __restrict__ psum, int kb)
{
    extern __shared__ uint32_t dsm[];
    const uint32_t dsma = (uint32_t)__cvta_generic_to_shared(dsm);

    const int tid = threadIdx.x;
    const int w   = tid >> 5;
    const int lid = tid & 31;
    const int g   = lid >> 2;      // 0..7
    const int tg  = lid & 3;       // 0..3
    const int wm  = w >> 1;        // 0..3
    const int wn  = w & 1;         // 0..1

    // ldmatrix per-lane row/col offsets
    const int a_r = (lid & 7) + ((lid >> 3) & 1) * 8;   // row within 16
    const int a_c = (lid >> 4) * 4;                      // u32 col (k half)
    const int b_r = (lid & 7) + (lid >> 4) * 8;          // row within 16
    const int b_c = ((lid >> 3) & 1) * 4;                // u32 col (k half)

    // A staging: 2 threads/row, 16 floats each
    const int arow = tid >> 1;            // 0..127
    const int asu  = (tid & 1) * 8;       // u32 offset
    const float* ap = A + (size_t)(bm + arow) * lda + asu * 2;
    // B staging: 4 threads/row, 8 floats each
    const int brow = tid >> 2;            // 0..63
    const int bsu  = (tid & 3) * 4;       // u32 offset
    const float* bp = B + (size_t)(bn + brow) * ldb + bsu * 2;

    float c[2][4][4];
#pragma unroll
    for (int mt = 0; mt < 2; ++mt)
#pragma unroll
        for (int nt = 0; nt < 4; ++nt)
#pragma unroll
            for (int i = 0; i < 4; ++i) c[mt][nt][i] = 0.0f;

    float4 pa[4], pb[2];
#pragma unroll
    for (int j = 0; j < 4; ++j) pa[j] = *(const float4*)(ap + j * 4);
#pragma unroll
    for (int j = 0; j < 2; ++j) pb[j] = *(const float4*)(bp + j * 4);

    // stage 0 fill
    {
        uint32_t* Ah = dsm;
        uint32_t* Al = dsm + 2560;
        uint32_t* Bh = dsm + 5120;
        uint32_t* Bl = dsm + 6400;
#pragma unroll
        for (int j = 0; j < 4; ++j)
            cvt_store_hl(&Ah[arow * SK + asu + j * 2], &Al[arow * SK + asu + j * 2], pa[j]);
#pragma unroll
        for (int j = 0; j < 2; ++j)
            cvt_store_hl(&Bh[brow * SK + bsu + j * 2], &Bl[brow * SK + bsu + j * 2], pb[j]);
    }
    __syncthreads();

    int stage = 0;
#pragma unroll 1
    for (int kt = 0; kt < kdim; kt += 32) {
        const bool nx = (kt + 32 < kdim);
        if (nx) {
#pragma unroll
            for (int j = 0; j < 4; ++j) pa[j] = *(const float4*)(ap + kt + 32 + j * 4);
#pragma unroll
            for (int j = 0; j < 2; ++j) pb[j] = *(const float4*)(bp + kt + 32 + j * 4);
        }

        const uint32_t sb = dsma + stage * (STAGE_U32 * 4);
        // byte addresses of fragment bases for this lane
        const uint32_t aAh = sb + ((wm * 32 + a_r) * SK + a_c) * 4;
        const uint32_t aAl = aAh + 2560 * 4;
        const uint32_t aBh = sb + 5120 * 4 + ((wn * 32 + b_r) * SK + b_c) * 4;
        const uint32_t aBl = aBh + 1280 * 4;

#pragma unroll
        for (int k16 = 0; k16 < 2; ++k16) {
            const uint32_t ko = k16 * 8 * 4;
            uint32_t ah[2][4], al[2][4], bh[2][4], bl[2][4];
#pragma unroll
            for (int mt = 0; mt < 2; ++mt) {
                ldsm4(ah[mt], aAh + mt * (16 * SK * 4) + ko);
                ldsm4(al[mt], aAl + mt * (16 * SK * 4) + ko);
            }
#pragma unroll
            for (int np = 0; np < 2; ++np) {
                ldsm4(bh[np], aBh + np * (16 * SK * 4) + ko);
                ldsm4(bl[np], aBl + np * (16 * SK * 4) + ko);
            }
            // pass 1: hi*hi (8 independent accumulators)
#pragma unroll
            for (int mt = 0; mt < 2; ++mt)
#pragma unroll
                for (int nt = 0; nt < 4; ++nt)
                    mma16816(c[mt][nt], ah[mt], &bh[nt >> 1][(nt & 1) * 2]);
            // pass 2: hi*lo
#pragma unroll
            for (int mt = 0; mt < 2; ++mt)
#pragma unroll
                for (int nt = 0; nt < 4; ++nt)
                    mma16816(c[mt][nt], ah[mt], &bl[nt >> 1][(nt & 1) * 2]);
            // pass 3: lo*hi
#pragma unroll
            for (int mt = 0; mt < 2; ++mt)
#pragma unroll
                for (int nt = 0; nt < 4; ++nt)
                    mma16816(c[mt][nt], al[mt], &bh[nt >> 1][(nt & 1) * 2]);
        }

        if (nx) {
            uint32_t* nb  = dsm + (stage ^ 1) * STAGE_U32;
            uint32_t* nAh = nb;
            uint32_t* nAl = nb + 2560;
            uint32_t* nBh = nb + 5120;
            uint32_t* nBl = nb + 6400;
#pragma unroll
            for (int j = 0; j < 4; ++j)
                cvt_store_hl(&nAh[arow * SK + asu + j * 2], &nAl[arow * SK + asu + j * 2], pa[j]);
#pragma unroll
            for (int j = 0; j < 2; ++j)
                cvt_store_hl(&nBh[brow * SK + bsu + j * 2], &nBl[brow * SK + bsu + j * 2], pb[j]);
        }
        __syncthreads();
        stage ^= 1;
    }

    // epilogue
    if (mode == 3) {
        float rs0[2], rs1[2];
        rs0[0] = rs0[1] = rs1[0] = rs1[1] = 0.0f;
#pragma unroll
        for (int mt = 0; mt < 2; ++mt) {
#pragma unroll
            for (int nt = 0; nt < 4; ++nt) {
                const int r0 = bm + wm * 32 + mt * 16 + g;
                const int n0 = bn + wn * 32 + nt * 8 + tg * 2;
                float e0 = __expf(c[mt][nt][0] * scale);
                float e1 = __expf(c[mt][nt][1] * scale);
                float e2 = __expf(c[mt][nt][2] * scale);
                float e3 = __expf(c[mt][nt][3] * scale);
                *(float2*)(C + (size_t)r0 * ldc + n0)       = make_float2(e0, e1);
                *(float2*)(C + (size_t)(r0 + 8) * ldc + n0) = make_float2(e2, e3);
                rs0[mt] += e0 + e1;
                rs1[mt] += e2 + e3;
            }
        }
        // reduce over the 4 tg lanes (same rows)
#pragma unroll
        for (int o = 1; o <= 2; o <<= 1) {
            rs0[0] += __shfl_xor_sync(0xffffffffu, rs0[0], o);
            rs0[1] += __shfl_xor_sync(0xffffffffu, rs0[1], o);
            rs1[0] += __shfl_xor_sync(0xffffffffu, rs1[0], o);
            rs1[1] += __shfl_xor_sync(0xffffffffu, rs1[1], o);
        }
        float* spart = (float*)(dsm + EXTRA_OFF);   // [128][2]
        if (tg == 0) {
#pragma unroll
            for (int mt = 0; mt < 2; ++mt) {
                spart[(wm * 32 + mt * 16 + g) * 2 + wn]     = rs0[mt];
                spart[(wm * 32 + mt * 16 + g + 8) * 2 + wn] = rs1[mt];
            }
        }
        __syncthreads();
        if (tid < 128)
            psum[(size_t)(bm + tid) * 32 + kb] = spart[tid * 2] + spart[tid * 2 + 1];
    } else {
#pragma unroll
        for (int mt = 0; mt < 2; ++mt) {
#pragma unroll
            for (int nt = 0; nt < 4; ++nt) {
                const int r0 = bm + wm * 32 + mt * 16 + g;
                const int n0 = bn + wn * 32 + nt * 8 + tg * 2;
                const float2 bb = *(const float2*)&bias[n0];
                float2 v0 = make_float2(c[mt][nt][0] + bb.x, c[mt][nt][1] + bb.y);
                float2 v1 = make_float2(c[mt][nt][2] + bb.x, c[mt][nt][3] + bb.y);
                if (mode == 1) {
                    const int h = n0 >> 6, d = n0 & 63;
                    const int b0 = r0 >> 11, s0 = r0 & 2047;
                    const int b1 = (r0 + 8) >> 11, s1 = (r0 + 8) & 2047;
                    *(float2*)(C + ((size_t)(b0 * HEADS + h) * SEQ + s0) * HDIM + d) = v0;
                    *(float2*)(C + ((size_t)(b1 * HEADS + h) * SEQ + s1) * HDIM + d) = v1;
                } else {
                    *(float2*)(C + (size_t)r0 * ldc + n0)       = v0;
                    *(float2*)(C + (size_t)(r0 + 8) * ldc + n0) = v1;
                }
            }
        }
    }
}

// Generic wrapper with z-strides (scores + O projection)
__global__ __launch_bounds__(256, 2) void gemm_bf16s_kernel(
    const float* __restrict__ Ag, const float* __restrict__ Bg,
    const float* __restrict__ bias, float* __restrict__ Cg,
    int lda, int ldb, int ldc, int kdim,
    size_t sAz, size_t sBz, size_t sCz,
    int mode, float scale, float* __restrict__ psum)
{
    const int z = blockIdx.z;
    float* pz = psum ? (psum + (size_t)z * SEQ * 32) : nullptr;
    gemm_core(Ag + (size_t)z * sAz, Bg + (size_t)z * sBz, bias,
              Cg + (size_t)z * sCz,
              lda, ldb, ldc, kdim, mode, scale,
              blockIdx.y * 128, blockIdx.x * 64, pz, blockIdx.x);
}

// Fused Q/K/V projection: blockIdx.z selects which projection
__global__ __launch_bounds__(256, 2) void qkv_proj_kernel(
    const float* __restrict__ q, const float* __restrict__ k,
    const float* __restrict__ v,
    const float* __restrict__ qw, const float* __restrict__ kw,
    const float* __restrict__ vw,
    const float* __restrict__ qb, const float* __restrict__ kb,
    const float* __restrict__ vb,
    float* __restrict__ dQ, float* __restrict__ dK, float* __restrict__ dV)
{
    const int z = blockIdx.z;
    const float* A = (z == 0) ? q : (z == 1) ? k : v;
    const float* W = (z == 0) ? qw : (z == 1) ? kw : vw;
    const float* B = (z == 0) ? qb : (z == 1) ? kb : vb;
    float* D = (z == 0) ? dQ : (z == 1) ? dK : dV;
    gemm_core(A, W, B, D, EMBED, EMBED, 0, EMBED, 1, 1.0f,
              blockIdx.y * 128, blockIdx.x * 64, nullptr, 0);
}

// ===========================================================================
// av: reads unnormalized exp scores, normalizes (writes back normalized
// attn weights in place), computes AO = P_norm @ V with split-bf16 MMA.
// CTA tile 128(q) x 64(d), BK=32, double-buffered + ldmatrix.
// ===========================================================================
__global__ __launch_bounds__(256, 2) void av_mma_kernel(
    float* __restrict__ attn, const float* __restrict__ Vg,
    const float* __restrict__ psum, float* __restrict__ ao)
{
    extern __shared__ uint32_t dsm[];
    const uint32_t dsma = (uint32_t)__cvta_generic_to_shared(dsm);
    float* s_inv = (float*)(dsm + EXTRA_OFF);   // [128]

    const int tid = threadIdx.x;
    const int w   = tid >> 5;
    const int lid = tid & 31;
    const int g   = lid >> 2;
    const int tg  = lid & 3;
    const int wm  = w >> 1;        // 0..3
    const int wn  = w & 1;         // 0..1

    const int a_r = (lid & 7) + ((lid >> 3) & 1) * 8;
    const int a_c = (lid >> 4) * 4;
    const int b_r = (lid & 7) + (lid >> 4) * 8;
    const int b_c = ((lid >> 3) & 1) * 4;

    const int z  = blockIdx.y;
    const int bm = blockIdx.x * 128;

    float* Wp = attn + (size_t)z * SEQ * SEQ + (size_t)bm * SEQ;
    const float* Vp = Vg + (size_t)z * SEQ * HDIM;

    // row inverse sums (deterministic reduction of 32 partials)
    if (tid < 128) {
        const float* pp = psum + ((size_t)z * SEQ + bm + tid) * 32;
        float s = 0.0f;
#pragma unroll
        for (int i = 0; i < 32; ++i) s += pp[i];
        s_inv[tid] = 1.0f / s;
    }
    __syncthreads();

    const int arow = tid >> 1;
    const int asu  = (tid & 1) * 8;
    float* apw = Wp + (size_t)arow * SEQ + asu * 2;
    const float inv = s_inv[arow];

    const int vn  = tid & 63;      // d index
    const int kp0 = tid >> 6;      // 0..3

    float c[2][4][4];
#pragma unroll
    for (int mt = 0; mt < 2; ++mt)
#pragma unroll
        for (int nt = 0; nt < 4; ++nt)
#pragma unroll
            for (int i = 0; i < 4; ++i) c[mt][nt][i] = 0.0f;

    float4 pa[4];
    float  pv[8];
#pragma unroll
    for (int j = 0; j < 4; ++j) pa[j] = *(const float4*)(apw + j * 4);
#pragma unroll
    for (int p = 0; p < 4; ++p) {
        const int kp = p * 4 + kp0;
        pv[p * 2]     = Vp[(size_t)(kp * 2) * HDIM + vn];
        pv[p * 2 + 1] = Vp[(size_t)(kp * 2 + 1) * HDIM + vn];
    }

    // normalize + write-back + stage helper
    auto stage_tiles = [&](uint32_t* base, float* wb_ptr) {
        uint32_t* Ah = base;
        uint32_t* Al = base + 2560;
#pragma unroll
        for (int j = 0; j < 4; ++j) {
            float4 vv = make_float4(pa[j].x * inv, pa[j].y * inv,
                                    pa[j].z * inv, pa[j].w * inv);
            *(float4*)(wb_ptr + j * 4) = vv;   // normalized attn weights
            cvt_store_hl(&Ah[arow * SK + asu + j * 2], &Al[arow * SK + asu + j * 2], vv);
        }
        uint32_t* Bh = base + 5120;
        uint32_t* Bl = base + 6400;
#pragma unroll
        for (int p = 0; p < 4; ++p) {
            const int kp = p * 4 + kp0;
            const float v0 = pv[p * 2], v1 = pv[p * 2 + 1];
            __nv_bfloat16 h0 = __float2bfloat16(v0);
            __nv_bfloat16 h1 = __float2bfloat16(v1);
            Bh[vn * SK + kp] = pack_bf16x2(h0, h1);
            Bl[vn * SK + kp] = pack_bf16x2(
                __float2bfloat16(v0 - __bfloat162float(h0)),
                __float2bfloat16(v1 - __bfloat162float(h1)));
        }
    };

    stage_tiles(dsm, apw);
    __syncthreads();

    int stage = 0;
#pragma unroll 1
    for (int kt = 0; kt < SEQ; kt += 32) {
        const bool nx = (kt + 32 < SEQ);
        if (nx) {
#pragma unroll
            for (int j = 0; j < 4; ++j)
                pa[j] = *(const float4*)(apw + kt + 32 + j * 4);
#pragma unroll
            for (int p = 0; p < 4; ++p) {
                const int kp = p * 4 + kp0;
                pv[p * 2]     = Vp[(size_t)(kt + 32 + kp * 2) * HDIM + vn];
                pv[p * 2 + 1] = Vp[(size_t)(kt + 32 + kp * 2 + 1) * HDIM + vn];
            }
        }

        const uint32_t sb = dsma + stage * (STAGE_U32 * 4);
        const uint32_t aAh = sb + ((wm * 32 + a_r) * SK + a_c) * 4;
        const uint32_t aAl = aAh + 2560 * 4;
        const uint32_t aBh = sb + 5120 * 4 + ((wn * 32 + b_r) * SK + b_c) * 4;
        const uint32_t aBl = aBh + 1280 * 4;

#pragma unroll
        for (int k16 = 0; k16 < 2; ++k16) {
            const uint32_t ko = k16 * 8 * 4;
            uint32_t ah[2][4], al[2][4], bh[2][4], bl[2][4];
#pragma unroll
            for (int mt = 0; mt < 2; ++mt) {
                ldsm4(ah[mt], aAh + mt * (16 * SK * 4) + ko);
                ldsm4(al[mt], aAl + mt * (16 * SK * 4) + ko);
            }
#pragma unroll
            for (int np = 0; np < 2; ++np) {
                ldsm4(bh[np], aBh + np * (16 * SK * 4) + ko);
                ldsm4(bl[np], aBl + np * (16 * SK * 4) + ko);
            }
#pragma unroll
            for (int mt = 0; mt < 2; ++mt)
#pragma unroll
                for (int nt = 0; nt < 4; ++nt)
                    mma16816(c[mt][nt], ah[mt], &bh[nt >> 1][(nt & 1) * 2]);
#pragma unroll
            for (int mt = 0; mt < 2; ++mt)
#pragma unroll
                for (int nt = 0; nt < 4; ++nt)
                    mma16816(c[mt][nt], ah[mt], &bl[nt >> 1][(nt & 1) * 2]);
#pragma unroll
            for (int mt = 0; mt < 2; ++mt)
#pragma unroll
                for (int nt = 0; nt < 4; ++nt)
                    mma16816(c[mt][nt], al[mt], &bh[nt >> 1][(nt & 1) * 2]);
        }

        if (nx)
            stage_tiles(dsm + (stage ^ 1) * STAGE_U32, apw + kt + 32);
        __syncthreads();
        stage ^= 1;
    }

    const int b = z >> 4, h = z & 15;
#pragma unroll
    for (int mt = 0; mt < 2; ++mt) {
#pragma unroll
        for (int nt = 0; nt < 4; ++nt) {
            const int q0 = bm + wm * 32 + mt * 16 + g;
            const int d0 = wn * 32 + nt * 8 + tg * 2;
            float* p0 = ao + ((size_t)(b * SEQ + q0)) * EMBED + h * HDIM + d0;
            float* p1 = ao + ((size_t)(b * SEQ + q0 + 8)) * EMBED + h * HDIM + d0;
            *(float2*)p0 = make_float2(c[mt][nt][0], c[mt][nt][1]);
            *(float2*)p1 = make_float2(c[mt][nt][2], c[mt][nt][3]);
        }
    }
}

// ---------------------------------------------------------------------------
// launch
// ---------------------------------------------------------------------------
extern "C" void kernel_launch(void* const* d_in, const int* in_sizes, int n_in,
                              void* d_out, int out_size)
{
    (void)in_sizes; (void)n_in; (void)out_size;
    const float* query = (const float*)d_in[0];
    const float* key   = (const float*)d_in[1];
    const float* value = (const float*)d_in[2];
    const float* q_w   = (const float*)d_in[3];
    const float* q_b   = (const float*)d_in[4];
    const float* k_w   = (const float*)d_in[5];
    const float* k_b   = (const float*)d_in[6];
    const float* v_w   = (const float*)d_in[7];
    const float* v_b   = (const float*)d_in[8];
    const float* o_w   = (const float*)d_in[9];
    const float* o_b   = (const float*)d_in[10];

    float* out  = (float*)d_out;                 // [B,S,E]
    float* attn = out + OUT_ELEMS;               // [B,H,S,S]

    float *pQ, *pK, *pV, *pAO, *pPS;
    cudaGetSymbolAddress((void**)&pQ, g_Q);
    cudaGetSymbolAddress((void**)&pK, g_K);
    cudaGetSymbolAddress((void**)&pV, g_V);
    cudaGetSymbolAddress((void**)&pAO, g_AO);
    cudaGetSymbolAddress((void**)&pPS, g_psum);

    static bool attr_done = false;
    if (!attr_done) {
        cudaFuncSetAttribute(qkv_proj_kernel,
                             cudaFuncAttributeMaxDynamicSharedMemorySize, GEMM_SMEM);
        cudaFuncSetAttribute(gemm_bf16s_kernel,
                             cudaFuncAttributeMaxDynamicSharedMemorySize, GEMM_SMEM);
        cudaFuncSetAttribute(av_mma_kernel,
                             cudaFuncAttributeMaxDynamicSharedMemorySize, AV_SMEM);
        attr_done = true;
    }

    // 1) fused Q/K/V projections (mode 1, split-head stores)
    dim3 qkvgrid(EMBED / 64, MTOT / 128, 3);     // (16, 32, 3)
    qkv_proj_kernel<<<qkvgrid, 256, GEMM_SMEM>>>(query, key, value,
                                                 q_w, k_w, v_w, q_b, k_b, v_b,
                                                 pQ, pK, pV);

    // 2) scores: attn[z] = exp((Q_z @ K_z^T) * 0.125) unnormalized + psum
    dim3 sgrid(SEQ / 64, SEQ / 128, BATCH * HEADS);  // (32, 16, 32)
    gemm_bf16s_kernel<<<sgrid, 256, GEMM_SMEM>>>(pQ, pK, nullptr, attn,
                                                 HDIM, HDIM, SEQ, HDIM,
                                                 (size_t)SEQ * HDIM, (size_t)SEQ * HDIM,
                                                 (size_t)SEQ * SEQ, 3, 0.125f, pPS);

    // 3) av: normalize attn in place + AO = P @ V
    dim3 avgrid(SEQ / 128, BATCH * HEADS);       // (16, 32)
    av_mma_kernel<<<avgrid, 256, AV_SMEM>>>(attn, pV, pPS, pAO);

    // 4) output projection (mode 0)
    dim3 ogrid(EMBED / 64, MTOT / 128, 1);       // (16, 32)
    gemm_bf16s_kernel<<<ogrid, 256, GEMM_SMEM>>>(pAO, o_w, o_b, out,
                                                 EMBED, EMBED, EMBED, EMBED, 0, 0, 0,
                                                 0, 1.0f, nullptr);
}

// round 13
// speedup vs baseline: 1.1793x; 1.0044x over previous
#include <cuda_runtime.h>
#include <cuda_bf16.h>
#include <cstdint>
#include <cstddef>

// Problem constants
#define BATCH   2
#define SEQ     2048
#define EMBED   1024
#define HEADS   16
#define HDIM    64
#define MTOT    (BATCH * SEQ)          // 4096
#define OUT_ELEMS   ((size_t)BATCH * SEQ * EMBED)                    // 4,194,304

// Scratch
__device__ float g_Q[BATCH * HEADS * SEQ * HDIM];
__device__ float g_K[BATCH * HEADS * SEQ * HDIM];
__device__ float g_V[BATCH * HEADS * SEQ * HDIM];
__device__ float g_AO[BATCH * SEQ * EMBED];
// partial row sums of exp(scores): [z][q][16 k-blocks of 128]
__device__ float g_psum[(size_t)BATCH * HEADS * SEQ * 32];

// ===========================================================================
// helpers
// ===========================================================================
__device__ __forceinline__ uint32_t pack_bf16x2(__nv_bfloat16 a, __nv_bfloat16 b) {
    __nv_bfloat162 t;
    t.x = a; t.y = b;
    return *reinterpret_cast<uint32_t*>(&t);
}

// hi/lo split of a float4 -> two u32 each (pairs along k)
__device__ __forceinline__ void cvt_store_hl(uint32_t* hi, uint32_t* lo, float4 v) {
    __nv_bfloat16 hx = __float2bfloat16(v.x);
    __nv_bfloat16 hy = __float2bfloat16(v.y);
    __nv_bfloat16 hz = __float2bfloat16(v.z);
    __nv_bfloat16 hw = __float2bfloat16(v.w);
    hi[0] = pack_bf16x2(hx, hy);
    hi[1] = pack_bf16x2(hz, hw);
    lo[0] = pack_bf16x2(__float2bfloat16(v.x - __bfloat162float(hx)),
                        __float2bfloat16(v.y - __bfloat162float(hy)));
    lo[1] = pack_bf16x2(__float2bfloat16(v.z - __bfloat162float(hz)),
                        __float2bfloat16(v.w - __bfloat162float(hw)));
}

// mma.sync m16n8k16 bf16 -> f32, C += A*B
__device__ __forceinline__ void mma16816(float* c, const uint32_t* a, const uint32_t* b) {
    asm volatile(
        "mma.sync.aligned.m16n8k16.row.col.f32.bf16.bf16.f32 "
        "{%0,%1,%2,%3}, {%4,%5,%6,%7}, {%8,%9}, {%0,%1,%2,%3};\n"
        : "+f"(c[0]), "+f"(c[1]), "+f"(c[2]), "+f"(c[3])
        : "r"(a[0]), "r"(a[1]), "r"(a[2]), "r"(a[3]), "r"(b[0]), "r"(b[1]));
}

// ldmatrix x4 (non-transposed)
__device__ __forceinline__ void ldsm4(uint32_t* r, uint32_t saddr) {
    asm volatile("ldmatrix.sync.aligned.m8n8.x4.shared.b16 {%0,%1,%2,%3}, [%4];"
                 : "=r"(r[0]), "=r"(r[1]), "=r"(r[2]), "=r"(r[3]) : "r"(saddr));
}

// smem row stride in u32 for BK=32 tiles: 16 data + 4 pad (conflict-free)
#define SK 20

// ---- big GEMM (128x128) smem layout, u32 units
#define G_STAGE  10240              // (128+128)*SK*2
#define G_AH     0
#define G_AL     2560
#define G_BH     5120
#define G_BL     7680
#define G_EXTRA  20480              // after two stages
#define GEMM_SMEM ((G_EXTRA + 512) * 4)

// ---- av (128x64) smem layout
#define AV_STAGE 7680               // 128*SK*2 + 64*SK*2
#define AV_EXTRA 15360
#define AV_SMEM  ((AV_EXTRA + 128) * 4)

// ===========================================================================
// Core split-bf16 GEMM tile: C[128, 128] = A[128, Kd] * B[128, Kd]^T
// 256 threads, 8 warps as 2m x 4n, warp tile 64x32, 64 accumulators.
// Double-buffered smem pipeline, ldmatrix fragment loads, pass-reordered MMAs.
// mode 0: C[r*ldc+n] = acc + bias[n]
// mode 1: split-head store to [B,H,S,Dh], + bias[n]
// mode 3: C = exp(acc*scale) (unnormalized), write partial row sums to psum
// ===========================================================================
__device__ __forceinline__ void gemm_core(
    const float* __restrict__ A, const float* __restrict__ B,
    const float* __restrict__ bias, float* __restrict__ C,
    int lda, int ldb, int ldc, int kdim, int mode, float scale,
    int bm, int bn, float* __restrict__ psum, int kb)
{
    extern __shared__ uint32_t dsm[];
    const uint32_t dsma = (uint32_t)__cvta_generic_to_shared(dsm);

    const int tid = threadIdx.x;
    const int w   = tid >> 5;
    const int lid = tid & 31;
    const int g   = lid >> 2;      // 0..7
    const int tg  = lid & 3;       // 0..3
    const int wm  = w >> 2;        // 0..1  (M offset wm*64)
    const int wn  = w & 3;         // 0..3  (N offset wn*32)

    // ldmatrix per-lane row/col offsets
    const int a_r = (lid & 7) + ((lid >> 3) & 1) * 8;   // row within 16
    const int a_c = (lid >> 4) * 4;                      // u32 col (k half)
    const int b_r = (lid & 7) + (lid >> 4) * 8;          // row within 16
    const int b_c = ((lid >> 3) & 1) * 4;                // u32 col (k half)

    // A/B staging: 2 threads/row, 16 floats each (128 rows each)
    const int srow = tid >> 1;            // 0..127
    const int ssu  = (tid & 1) * 8;       // u32 offset
    const float* ap = A + (size_t)(bm + srow) * lda + ssu * 2;
    const float* bp = B + (size_t)(bn + srow) * ldb + ssu * 2;

    float c[4][4][4];
#pragma unroll
    for (int mt = 0; mt < 4; ++mt)
#pragma unroll
        for (int nt = 0; nt < 4; ++nt)
#pragma unroll
            for (int i = 0; i < 4; ++i) c[mt][nt][i] = 0.0f;

    float4 pa[4], pb[4];
#pragma unroll
    for (int j = 0; j < 4; ++j) {
        pa[j] = *(const float4*)(ap + j * 4);
        pb[j] = *(const float4*)(bp + j * 4);
    }

    // stage 0 fill
    {
        uint32_t* Ah = dsm + G_AH;
        uint32_t* Al = dsm + G_AL;
        uint32_t* Bh = dsm + G_BH;
        uint32_t* Bl = dsm + G_BL;
#pragma unroll
        for (int j = 0; j < 4; ++j) {
            cvt_store_hl(&Ah[srow * SK + ssu + j * 2], &Al[srow * SK + ssu + j * 2], pa[j]);
            cvt_store_hl(&Bh[srow * SK + ssu + j * 2], &Bl[srow * SK + ssu + j * 2], pb[j]);
        }
    }
    __syncthreads();

    int stage = 0;
#pragma unroll 1
    for (int kt = 0; kt < kdim; kt += 32) {
        const bool nx = (kt + 32 < kdim);
        if (nx) {
#pragma unroll
            for (int j = 0; j < 4; ++j) {
                pa[j] = *(const float4*)(ap + kt + 32 + j * 4);
                pb[j] = *(const float4*)(bp + kt + 32 + j * 4);
            }
        }

        const uint32_t sb = dsma + stage * (G_STAGE * 4);
        const uint32_t aAh = sb + ((a_r) * SK + a_c) * 4 + (wm * 64) * (SK * 4);
        const uint32_t aAl = aAh + G_AL * 4;
        const uint32_t aBh = sb + G_BH * 4 + ((wn * 32 + b_r) * SK + b_c) * 4;
        const uint32_t aBl = aBh + (G_BL - G_BH) * 4;

#pragma unroll
        for (int k16 = 0; k16 < 2; ++k16) {
            const uint32_t ko = k16 * 8 * 4;
            uint32_t ah[4][4], al[4][4], bh[2][4], bl[2][4];
#pragma unroll
            for (int mt = 0; mt < 4; ++mt) {
                ldsm4(ah[mt], aAh + mt * (16 * SK * 4) + ko);
                ldsm4(al[mt], aAl + mt * (16 * SK * 4) + ko);
            }
#pragma unroll
            for (int np = 0; np < 2; ++np) {
                ldsm4(bh[np], aBh + np * (16 * SK * 4) + ko);
                ldsm4(bl[np], aBl + np * (16 * SK * 4) + ko);
            }
            // pass 1: hi*hi (16 independent accumulators)
#pragma unroll
            for (int mt = 0; mt < 4; ++mt)
#pragma unroll
                for (int nt = 0; nt < 4; ++nt)
                    mma16816(c[mt][nt], ah[mt], &bh[nt >> 1][(nt & 1) * 2]);
            // pass 2: hi*lo
#pragma unroll
            for (int mt = 0; mt < 4; ++mt)
#pragma unroll
                for (int nt = 0; nt < 4; ++nt)
                    mma16816(c[mt][nt], ah[mt], &bl[nt >> 1][(nt & 1) * 2]);
            // pass 3: lo*hi
#pragma unroll
            for (int mt = 0; mt < 4; ++mt)
#pragma unroll
                for (int nt = 0; nt < 4; ++nt)
                    mma16816(c[mt][nt], al[mt], &bh[nt >> 1][(nt & 1) * 2]);
        }

        if (nx) {
            uint32_t* nb  = dsm + (stage ^ 1) * G_STAGE;
            uint32_t* nAh = nb + G_AH;
            uint32_t* nAl = nb + G_AL;
            uint32_t* nBh = nb + G_BH;
            uint32_t* nBl = nb + G_BL;
#pragma unroll
            for (int j = 0; j < 4; ++j) {
                cvt_store_hl(&nAh[srow * SK + ssu + j * 2], &nAl[srow * SK + ssu + j * 2], pa[j]);
                cvt_store_hl(&nBh[srow * SK + ssu + j * 2], &nBl[srow * SK + ssu + j * 2], pb[j]);
            }
        }
        __syncthreads();
        stage ^= 1;
    }

    // epilogue
    if (mode == 3) {
        float rs0[4], rs1[4];
#pragma unroll
        for (int mt = 0; mt < 4; ++mt) { rs0[mt] = 0.0f; rs1[mt] = 0.0f; }
#pragma unroll
        for (int mt = 0; mt < 4; ++mt) {
#pragma unroll
            for (int nt = 0; nt < 4; ++nt) {
                const int r0 = bm + wm * 64 + mt * 16 + g;
                const int n0 = bn + wn * 32 + nt * 8 + tg * 2;
                float e0 = __expf(c[mt][nt][0] * scale);
                float e1 = __expf(c[mt][nt][1] * scale);
                float e2 = __expf(c[mt][nt][2] * scale);
                float e3 = __expf(c[mt][nt][3] * scale);
                *(float2*)(C + (size_t)r0 * ldc + n0)       = make_float2(e0, e1);
                *(float2*)(C + (size_t)(r0 + 8) * ldc + n0) = make_float2(e2, e3);
                rs0[mt] += e0 + e1;
                rs1[mt] += e2 + e3;
            }
        }
        // reduce over the 4 tg lanes (same rows)
#pragma unroll
        for (int o = 1; o <= 2; o <<= 1) {
#pragma unroll
            for (int mt = 0; mt < 4; ++mt) {
                rs0[mt] += __shfl_xor_sync(0xffffffffu, rs0[mt], o);
                rs1[mt] += __shfl_xor_sync(0xffffffffu, rs1[mt], o);
            }
        }
        float* spart = (float*)(dsm + G_EXTRA);   // [128][4]
        if (tg == 0) {
#pragma unroll
            for (int mt = 0; mt < 4; ++mt) {
                spart[(wm * 64 + mt * 16 + g) * 4 + wn]     = rs0[mt];
                spart[(wm * 64 + mt * 16 + g + 8) * 4 + wn] = rs1[mt];
            }
        }
        __syncthreads();
        if (tid < 128) {
            const float* sp = spart + tid * 4;
            psum[(size_t)(bm + tid) * 32 + kb] = (sp[0] + sp[1]) + (sp[2] + sp[3]);
        }
    } else {
#pragma unroll
        for (int mt = 0; mt < 4; ++mt) {
#pragma unroll
            for (int nt = 0; nt < 4; ++nt) {
                const int r0 = bm + wm * 64 + mt * 16 + g;
                const int n0 = bn + wn * 32 + nt * 8 + tg * 2;
                const float2 bb = *(const float2*)&bias[n0];
                float2 v0 = make_float2(c[mt][nt][0] + bb.x, c[mt][nt][1] + bb.y);
                float2 v1 = make_float2(c[mt][nt][2] + bb.x, c[mt][nt][3] + bb.y);
                if (mode == 1) {
                    const int h = n0 >> 6, d = n0 & 63;
                    const int b0 = r0 >> 11, s0 = r0 & 2047;
                    const int b1 = (r0 + 8) >> 11, s1 = (r0 + 8) & 2047;
                    *(float2*)(C + ((size_t)(b0 * HEADS + h) * SEQ + s0) * HDIM + d) = v0;
                    *(float2*)(C + ((size_t)(b1 * HEADS + h) * SEQ + s1) * HDIM + d) = v1;
                } else {
                    *(float2*)(C + (size_t)r0 * ldc + n0)       = v0;
                    *(float2*)(C + (size_t)(r0 + 8) * ldc + n0) = v1;
                }
            }
        }
    }
}

// Generic wrapper with z-strides (scores + O projection)
__global__ __launch_bounds__(256, 1) void gemm_bf16s_kernel(
    const float* __restrict__ Ag, const float* __restrict__ Bg,
    const float* __restrict__ bias, float* __restrict__ Cg,
    int lda, int ldb, int ldc, int kdim,
    size_t sAz, size_t sBz, size_t sCz,
    int mode, float scale, float* __restrict__ psum)
{
    const int z = blockIdx.z;
    float* pz = psum ? (psum + (size_t)z * SEQ * 32) : nullptr;
    gemm_core(Ag + (size_t)z * sAz, Bg + (size_t)z * sBz, bias,
              Cg + (size_t)z * sCz,
              lda, ldb, ldc, kdim, mode, scale,
              blockIdx.y * 128, blockIdx.x * 128, pz, blockIdx.x);
}

// Fused Q/K/V projection: blockIdx.z selects which projection
__global__ __launch_bounds__(256, 1) void qkv_proj_kernel(
    const float* __restrict__ q, const float* __restrict__ k,
    const float* __restrict__ v,
    const float* __restrict__ qw, const float* __restrict__ kw,
    const float* __restrict__ vw,
    const float* __restrict__ qb, const float* __restrict__ kb,
    const float* __restrict__ vb,
    float* __restrict__ dQ, float* __restrict__ dK, float* __restrict__ dV)
{
    const int z = blockIdx.z;
    const float* A = (z == 0) ? q : (z == 1) ? k : v;
    const float* W = (z == 0) ? qw : (z == 1) ? kw : vw;
    const float* B = (z == 0) ? qb : (z == 1) ? kb : vb;
    float* D = (z == 0) ? dQ : (z == 1) ? dK : dV;
    gemm_core(A, W, B, D, EMBED, EMBED, 0, EMBED, 1, 1.0f,
              blockIdx.y * 128, blockIdx.x * 128, nullptr, 0);
}

// ===========================================================================
// av: reads unnormalized exp scores, normalizes (writes back normalized
// attn weights in place), computes AO = P_norm @ V with split-bf16 MMA.
// CTA tile 128(q) x 64(d), BK=32, double-buffered + ldmatrix.
// ===========================================================================
__global__ __launch_bounds__(256, 2) void av_mma_kernel(
    float* __restrict__ attn, const float* __restrict__ Vg,
    const float* __restrict__ psum, float* __restrict__ ao)
{
    extern __shared__ uint32_t dsm[];
    const uint32_t dsma = (uint32_t)__cvta_generic_to_shared(dsm);
    float* s_inv = (float*)(dsm + AV_EXTRA);   // [128]

    const int tid = threadIdx.x;
    const int w   = tid >> 5;
    const int lid = tid & 31;
    const int g   = lid >> 2;
    const int tg  = lid & 3;
    const int wm  = w >> 1;        // 0..3
    const int wn  = w & 1;         // 0..1

    const int a_r = (lid & 7) + ((lid >> 3) & 1) * 8;
    const int a_c = (lid >> 4) * 4;
    const int b_r = (lid & 7) + (lid >> 4) * 8;
    const int b_c = ((lid >> 3) & 1) * 4;

    const int z  = blockIdx.y;
    const int bm = blockIdx.x * 128;

    float* Wp = attn + (size_t)z * SEQ * SEQ + (size_t)bm * SEQ;
    const float* Vp = Vg + (size_t)z * SEQ * HDIM;

    // row inverse sums (deterministic reduction of 16 partials)
    if (tid < 128) {
        const float* pp = psum + ((size_t)z * SEQ + bm + tid) * 32;
        float s = 0.0f;
#pragma unroll
        for (int i = 0; i < 16; ++i) s += pp[i];
        s_inv[tid] = 1.0f / s;
    }
    __syncthreads();

    const int arow = tid >> 1;
    const int asu  = (tid & 1) * 8;
    float* apw = Wp + (size_t)arow * SEQ + asu * 2;
    const float inv = s_inv[arow];

    const int vn  = tid & 63;      // d index
    const int kp0 = tid >> 6;      // 0..3

    float c[2][4][4];
#pragma unroll
    for (int mt = 0; mt < 2; ++mt)
#pragma unroll
        for (int nt = 0; nt < 4; ++nt)
#pragma unroll
            for (int i = 0; i < 4; ++i) c[mt][nt][i] = 0.0f;

    float4 pa[4];
    float  pv[8];
#pragma unroll
    for (int j = 0; j < 4; ++j) pa[j] = *(const float4*)(apw + j * 4);
#pragma unroll
    for (int p = 0; p < 4; ++p) {
        const int kp = p * 4 + kp0;
        pv[p * 2]     = Vp[(size_t)(kp * 2) * HDIM + vn];
        pv[p * 2 + 1] = Vp[(size_t)(kp * 2 + 1) * HDIM + vn];
    }

    // normalize + write-back + stage helper
    auto stage_tiles = [&](uint32_t* base, float* wb_ptr) {
        uint32_t* Ah = base;
        uint32_t* Al = base + 2560;
#pragma unroll
        for (int j = 0; j < 4; ++j) {
            float4 vv = make_float4(pa[j].x * inv, pa[j].y * inv,
                                    pa[j].z * inv, pa[j].w * inv);
            *(float4*)(wb_ptr + j * 4) = vv;   // normalized attn weights
            cvt_store_hl(&Ah[arow * SK + asu + j * 2], &Al[arow * SK + asu + j * 2], vv);
        }
        uint32_t* Bh = base + 5120;
        uint32_t* Bl = base + 6400;
#pragma unroll
        for (int p = 0; p < 4; ++p) {
            const int kp = p * 4 + kp0;
            const float v0 = pv[p * 2], v1 = pv[p * 2 + 1];
            __nv_bfloat16 h0 = __float2bfloat16(v0);
            __nv_bfloat16 h1 = __float2bfloat16(v1);
            Bh[vn * SK + kp] = pack_bf16x2(h0, h1);
            Bl[vn * SK + kp] = pack_bf16x2(
                __float2bfloat16(v0 - __bfloat162float(h0)),
                __float2bfloat16(v1 - __bfloat162float(h1)));
        }
    };

    stage_tiles(dsm, apw);
    __syncthreads();

    int stage = 0;
#pragma unroll 1
    for (int kt = 0; kt < SEQ; kt += 32) {
        const bool nx = (kt + 32 < SEQ);
        if (nx) {
#pragma unroll
            for (int j = 0; j < 4; ++j)
                pa[j] = *(const float4*)(apw + kt + 32 + j * 4);
#pragma unroll
            for (int p = 0; p < 4; ++p) {
                const int kp = p * 4 + kp0;
                pv[p * 2]     = Vp[(size_t)(kt + 32 + kp * 2) * HDIM + vn];
                pv[p * 2 + 1] = Vp[(size_t)(kt + 32 + kp * 2 + 1) * HDIM + vn];
            }
        }

        const uint32_t sb = dsma + stage * (AV_STAGE * 4);
        const uint32_t aAh = sb + ((wm * 32 + a_r) * SK + a_c) * 4;
        const uint32_t aAl = aAh + 2560 * 4;
        const uint32_t aBh = sb + 5120 * 4 + ((wn * 32 + b_r) * SK + b_c) * 4;
        const uint32_t aBl = aBh + 1280 * 4;

#pragma unroll
        for (int k16 = 0; k16 < 2; ++k16) {
            const uint32_t ko = k16 * 8 * 4;
            uint32_t ah[2][4], al[2][4], bh[2][4], bl[2][4];
#pragma unroll
            for (int mt = 0; mt < 2; ++mt) {
                ldsm4(ah[mt], aAh + mt * (16 * SK * 4) + ko);
                ldsm4(al[mt], aAl + mt * (16 * SK * 4) + ko);
            }
#pragma unroll
            for (int np = 0; np < 2; ++np) {
                ldsm4(bh[np], aBh + np * (16 * SK * 4) + ko);
                ldsm4(bl[np], aBl + np * (16 * SK * 4) + ko);
            }
#pragma unroll
            for (int mt = 0; mt < 2; ++mt)
#pragma unroll
                for (int nt = 0; nt < 4; ++nt)
                    mma16816(c[mt][nt], ah[mt], &bh[nt >> 1][(nt & 1) * 2]);
#pragma unroll
            for (int mt = 0; mt < 2; ++mt)
#pragma unroll
                for (int nt = 0; nt < 4; ++nt)
                    mma16816(c[mt][nt], ah[mt], &bl[nt >> 1][(nt & 1) * 2]);
#pragma unroll
            for (int mt = 0; mt < 2; ++mt)
#pragma unroll
                for (int nt = 0; nt < 4; ++nt)
                    mma16816(c[mt][nt], al[mt], &bh[nt >> 1][(nt & 1) * 2]);
        }

        if (nx)
            stage_tiles(dsm + (stage ^ 1) * AV_STAGE, apw + kt + 32);
        __syncthreads();
        stage ^= 1;
    }

    const int b = z >> 4, h = z & 15;
#pragma unroll
    for (int mt = 0; mt < 2; ++mt) {
#pragma unroll
        for (int nt = 0; nt < 4; ++nt) {
            const int q0 = bm + wm * 32 + mt * 16 + g;
            const int d0 = wn * 32 + nt * 8 + tg * 2;
            float* p0 = ao + ((size_t)(b * SEQ + q0)) * EMBED + h * HDIM + d0;
            float* p1 = ao + ((size_t)(b * SEQ + q0 + 8)) * EMBED + h * HDIM + d0;
            *(float2*)p0 = make_float2(c[mt][nt][0], c[mt][nt][1]);
            *(float2*)p1 = make_float2(c[mt][nt][2], c[mt][nt][3]);
        }
    }
}

// ---------------------------------------------------------------------------
// launch
// ---------------------------------------------------------------------------
extern "C" void kernel_launch(void* const* d_in, const int* in_sizes, int n_in,
                              void* d_out, int out_size)
{
    (void)in_sizes; (void)n_in; (void)out_size;
    const float* query = (const float*)d_in[0];
    const float* key   = (const float*)d_in[1];
    const float* value = (const float*)d_in[2];
    const float* q_w   = (const float*)d_in[3];
    const float* q_b   = (const float*)d_in[4];
    const float* k_w   = (const float*)d_in[5];
    const float* k_b   = (const float*)d_in[6];
    const float* v_w   = (const float*)d_in[7];
    const float* v_b   = (const float*)d_in[8];
    const float* o_w   = (const float*)d_in[9];
    const float* o_b   = (const float*)d_in[10];

    float* out  = (float*)d_out;                 // [B,S,E]
    float* attn = out + OUT_ELEMS;               // [B,H,S,S]

    float *pQ, *pK, *pV, *pAO, *pPS;
    cudaGetSymbolAddress((void**)&pQ, g_Q);
    cudaGetSymbolAddress((void**)&pK, g_K);
    cudaGetSymbolAddress((void**)&pV, g_V);
    cudaGetSymbolAddress((void**)&pAO, g_AO);
    cudaGetSymbolAddress((void**)&pPS, g_psum);

    static bool attr_done = false;
    if (!attr_done) {
        cudaFuncSetAttribute(qkv_proj_kernel,
                             cudaFuncAttributeMaxDynamicSharedMemorySize, GEMM_SMEM);
        cudaFuncSetAttribute(gemm_bf16s_kernel,
                             cudaFuncAttributeMaxDynamicSharedMemorySize, GEMM_SMEM);
        cudaFuncSetAttribute(av_mma_kernel,
                             cudaFuncAttributeMaxDynamicSharedMemorySize, AV_SMEM);
        attr_done = true;
    }

    // 1) fused Q/K/V projections (mode 1, split-head stores)
    dim3 qkvgrid(EMBED / 128, MTOT / 128, 3);    // (8, 32, 3)
    qkv_proj_kernel<<<qkvgrid, 256, GEMM_SMEM>>>(query, key, value,
                                                 q_w, k_w, v_w, q_b, k_b, v_b,
                                                 pQ, pK, pV);

    // 2) scores: attn[z] = exp((Q_z @ K_z^T) * 0.125) unnormalized + psum
    dim3 sgrid(SEQ / 128, SEQ / 128, BATCH * HEADS);  // (16, 16, 32)
    gemm_bf16s_kernel<<<sgrid, 256, GEMM_SMEM>>>(pQ, pK, nullptr, attn,
                                                 HDIM, HDIM, SEQ, HDIM,
                                                 (size_t)SEQ * HDIM, (size_t)SEQ * HDIM,
                                                 (size_t)SEQ * SEQ, 3, 0.125f, pPS);

    // 3) av: normalize attn in place + AO = P @ V
    dim3 avgrid(SEQ / 128, BATCH * HEADS);       // (16, 32)
    av_mma_kernel<<<avgrid, 256, AV_SMEM>>>(attn, pV, pPS, pAO);

    // 4) output projection (mode 0)
    dim3 ogrid(EMBED / 128, MTOT / 128, 1);      // (8, 32)
    gemm_bf16s_kernel<<<ogrid, 256, GEMM_SMEM>>>(pAO, o_w, o_b, out,
                                                 EMBED, EMBED, EMBED, EMBED, 0, 0, 0,
                                                 0, 1.0f, nullptr);
}

// round 14
// speedup vs baseline: 1.2094x; 1.0255x over previous
#include <cuda_runtime.h>
#include <cuda_bf16.h>
#include <cstdint>
#include <cstddef>

// Problem constants
#define BATCH   2
#define SEQ     2048
#define EMBED   1024
#define HEADS   16
#define HDIM    64
#define MTOT    (BATCH * SEQ)          // 4096
#define ZTOT    (BATCH * HEADS)        // 32
#define OUT_ELEMS   ((size_t)BATCH * SEQ * EMBED)                    // 4,194,304

// ---------------------------------------------------------------------------
// Pre-split bf16 hi/lo scratch (split once, consumed by all GEMMs)
// ---------------------------------------------------------------------------
__device__ __nv_bfloat16 g_Xh[3 * MTOT * EMBED];   // query|key|value
__device__ __nv_bfloat16 g_Xl[3 * MTOT * EMBED];
__device__ __nv_bfloat16 g_Wh[4 * EMBED * EMBED];  // qw|kw|vw|ow
__device__ __nv_bfloat16 g_Wl[4 * EMBED * EMBED];
__device__ __nv_bfloat16 g_Qh[ZTOT * SEQ * HDIM];  // [z][S][64]
__device__ __nv_bfloat16 g_Ql[ZTOT * SEQ * HDIM];
__device__ __nv_bfloat16 g_Kh[ZTOT * SEQ * HDIM];
__device__ __nv_bfloat16 g_Kl[ZTOT * SEQ * HDIM];
__device__ __nv_bfloat16 g_Vth[ZTOT * HDIM * SEQ]; // [z][64][S] (transposed)
__device__ __nv_bfloat16 g_Vtl[ZTOT * HDIM * SEQ];
__device__ __nv_bfloat16 g_AOh[MTOT * EMBED];      // [B,S,E]
__device__ __nv_bfloat16 g_AOl[MTOT * EMBED];
// partial row sums of exp(scores): [z][q][16 k-blocks of 128] (stride 32)
__device__ float g_psum[(size_t)ZTOT * SEQ * 32];

// ===========================================================================
// helpers
// ===========================================================================
__device__ __forceinline__ uint32_t pack_bf16x2(__nv_bfloat16 a, __nv_bfloat16 b) {
    __nv_bfloat162 t;
    t.x = a; t.y = b;
    return *reinterpret_cast<uint32_t*>(&t);
}

__device__ __forceinline__ void split2(float x, float y, uint32_t& h, uint32_t& l) {
    __nv_bfloat16 hx = __float2bfloat16(x);
    __nv_bfloat16 hy = __float2bfloat16(y);
    h = pack_bf16x2(hx, hy);
    l = pack_bf16x2(__float2bfloat16(x - __bfloat162float(hx)),
                    __float2bfloat16(y - __bfloat162float(hy)));
}

// hi/lo split of a float4 -> two u32 each (pairs along k)  (av P-staging)
__device__ __forceinline__ void cvt_store_hl(uint32_t* hi, uint32_t* lo, float4 v) {
    uint32_t h0, l0, h1, l1;
    split2(v.x, v.y, h0, l0);
    split2(v.z, v.w, h1, l1);
    hi[0] = h0; hi[1] = h1;
    lo[0] = l0; lo[1] = l1;
}

// mma.sync m16n8k16 bf16 -> f32, C += A*B
__device__ __forceinline__ void mma16816(float* c, const uint32_t* a, const uint32_t* b) {
    asm volatile(
        "mma.sync.aligned.m16n8k16.row.col.f32.bf16.bf16.f32 "
        "{%0,%1,%2,%3}, {%4,%5,%6,%7}, {%8,%9}, {%0,%1,%2,%3};\n"
        : "+f"(c[0]), "+f"(c[1]), "+f"(c[2]), "+f"(c[3])
        : "r"(a[0]), "r"(a[1]), "r"(a[2]), "r"(a[3]), "r"(b[0]), "r"(b[1]));
}

// ldmatrix x4 (non-transposed)
__device__ __forceinline__ void ldsm4(uint32_t* r, uint32_t saddr) {
    asm volatile("ldmatrix.sync.aligned.m8n8.x4.shared.b16 {%0,%1,%2,%3}, [%4];"
                 : "=r"(r[0]), "=r"(r[1]), "=r"(r[2]), "=r"(r[3]) : "r"(saddr));
}

// smem row stride in u32 for BK=32 tiles: 16 data + 4 pad (conflict-free)
#define SK 20

// ---- big GEMM (128x128) smem layout, u32 units
#define G_STAGE  10240              // (128+128)*SK*2
#define G_AH     0
#define G_AL     2560
#define G_BH     5120
#define G_BL     7680
#define G_EXTRA  20480
#define GEMM_SMEM ((G_EXTRA + 512) * 4)

// ---- av (128x64) smem layout
#define AV_STAGE 7680               // 128*SK*2 + 64*SK*2
#define AV_EXTRA 15360
#define AV_SMEM  ((AV_EXTRA + 128) * 4)

// ===========================================================================
// prep: split fp32 inputs/weights into bf16 hi/lo once.
// z 0..2 -> query/key/value (4M elems); z 3..6 -> qw/kw/vw/ow (1M elems)
// ===========================================================================
__global__ __launch_bounds__(256) void prep_split_kernel(
    const float* __restrict__ q, const float* __restrict__ k,
    const float* __restrict__ v,
    const float* __restrict__ qw, const float* __restrict__ kw,
    const float* __restrict__ vw, const float* __restrict__ ow)
{
    const int z = blockIdx.z;
    const float* src;
    __nv_bfloat16 *dh, *dl;
    int n4;
    if (z < 3) {
        src = (z == 0) ? q : (z == 1) ? k : v;
        dh = g_Xh + (size_t)z * MTOT * EMBED;
        dl = g_Xl + (size_t)z * MTOT * EMBED;
        n4 = MTOT * EMBED / 4;
    } else {
        const int wz = z - 3;
        src = (wz == 0) ? qw : (wz == 1) ? kw : (wz == 2) ? vw : ow;
        dh = g_Wh + (size_t)wz * EMBED * EMBED;
        dl = g_Wl + (size_t)wz * EMBED * EMBED;
        n4 = EMBED * EMBED / 4;
    }
    const int i = blockIdx.x * 256 + threadIdx.x;
    if (i >= n4) return;
    float4 f = ((const float4*)src)[i];
    uint32_t h01, l01, h23, l23;
    split2(f.x, f.y, h01, l01);
    split2(f.z, f.w, h23, l23);
    ((uint2*)dh)[i] = make_uint2(h01, h23);
    ((uint2*)dl)[i] = make_uint2(l01, l23);
}

// ===========================================================================
// Core split-bf16 GEMM tile: C[128, 128] = A[128, Kd] * B[128, Kd]^T
// Operands pre-split bf16 hi/lo in gmem -> staging is pure LDG.128/STS.128.
// 256 threads, 8 warps as 2m x 4n, warp tile 64x32.
// mode 0: Cf[r*ldc+n] = acc + bias[n]                 (fp32)
// mode 1: split-head store to Ch/Cl [z][S][64], + bias (bf16 hi/lo)
// mode 2: transposed split store to Ch/Cl [z][64][S], + bias (V)
// mode 3: Cf = exp(acc*scale) (unnormalized) + psum partials
// ===========================================================================
__device__ __forceinline__ void gemm_core_s(
    const __nv_bfloat16* __restrict__ Ah_g, const __nv_bfloat16* __restrict__ Al_g,
    const __nv_bfloat16* __restrict__ Bh_g, const __nv_bfloat16* __restrict__ Bl_g,
    const float* __restrict__ bias,
    float* __restrict__ Cf, __nv_bfloat16* __restrict__ Ch,
    __nv_bfloat16* __restrict__ Cl,
    int lda, int ldb, int ldc, int kdim, int mode, float scale,
    int bm, int bn, float* __restrict__ psum, int kb)
{
    extern __shared__ uint32_t dsm[];
    const uint32_t dsma = (uint32_t)__cvta_generic_to_shared(dsm);

    const int tid = threadIdx.x;
    const int w   = tid >> 5;
    const int lid = tid & 31;
    const int g   = lid >> 2;
    const int tg  = lid & 3;
    const int wm  = w >> 2;        // 0..1
    const int wn  = w & 3;         // 0..3

    const int a_r = (lid & 7) + ((lid >> 3) & 1) * 8;
    const int a_c = (lid >> 4) * 4;
    const int b_r = (lid & 7) + (lid >> 4) * 8;
    const int b_c = ((lid >> 3) & 1) * 4;

    // staging: 2 threads/row, 16 bf16 elems each
    const int srow = tid >> 1;
    const int ssu  = (tid & 1) * 8;       // u32 offset in smem row
    const __nv_bfloat16* aph = Ah_g + (size_t)(bm + srow) * lda + ssu * 2;
    const __nv_bfloat16* apl = Al_g + (size_t)(bm + srow) * lda + ssu * 2;
    const __nv_bfloat16* bph = Bh_g + (size_t)(bn + srow) * ldb + ssu * 2;
    const __nv_bfloat16* bpl = Bl_g + (size_t)(bn + srow) * ldb + ssu * 2;

    float c[4][4][4];
#pragma unroll
    for (int mt = 0; mt < 4; ++mt)
#pragma unroll
        for (int nt = 0; nt < 4; ++nt)
#pragma unroll
            for (int i = 0; i < 4; ++i) c[mt][nt][i] = 0.0f;

    uint4 pah[2], pal[2], pbh[2], pbl[2];
    pah[0] = *(const uint4*)(aph);     pah[1] = *(const uint4*)(aph + 8);
    pal[0] = *(const uint4*)(apl);     pal[1] = *(const uint4*)(apl + 8);
    pbh[0] = *(const uint4*)(bph);     pbh[1] = *(const uint4*)(bph + 8);
    pbl[0] = *(const uint4*)(bpl);     pbl[1] = *(const uint4*)(bpl + 8);

    auto stage = [&](int st) {
        uint32_t* b0 = dsm + st * G_STAGE;
        *(uint4*)&b0[G_AH + srow * SK + ssu]     = pah[0];
        *(uint4*)&b0[G_AH + srow * SK + ssu + 4] = pah[1];
        *(uint4*)&b0[G_AL + srow * SK + ssu]     = pal[0];
        *(uint4*)&b0[G_AL + srow * SK + ssu + 4] = pal[1];
        *(uint4*)&b0[G_BH + srow * SK + ssu]     = pbh[0];
        *(uint4*)&b0[G_BH + srow * SK + ssu + 4] = pbh[1];
        *(uint4*)&b0[G_BL + srow * SK + ssu]     = pbl[0];
        *(uint4*)&b0[G_BL + srow * SK + ssu + 4] = pbl[1];
    };
    stage(0);
    __syncthreads();

    int stg = 0;
#pragma unroll 1
    for (int kt = 0; kt < kdim; kt += 32) {
        const bool nx = (kt + 32 < kdim);
        if (nx) {
            pah[0] = *(const uint4*)(aph + kt + 32); pah[1] = *(const uint4*)(aph + kt + 40);
            pal[0] = *(const uint4*)(apl + kt + 32); pal[1] = *(const uint4*)(apl + kt + 40);
            pbh[0] = *(const uint4*)(bph + kt + 32); pbh[1] = *(const uint4*)(bph + kt + 40);
            pbl[0] = *(const uint4*)(bpl + kt + 32); pbl[1] = *(const uint4*)(bpl + kt + 40);
        }

        const uint32_t sb = dsma + stg * (G_STAGE * 4);
        const uint32_t aAh = sb + ((a_r) * SK + a_c) * 4 + (wm * 64) * (SK * 4);
        const uint32_t aAl = aAh + G_AL * 4;
        const uint32_t aBh = sb + G_BH * 4 + ((wn * 32 + b_r) * SK + b_c) * 4;
        const uint32_t aBl = aBh + (G_BL - G_BH) * 4;

#pragma unroll
        for (int k16 = 0; k16 < 2; ++k16) {
            const uint32_t ko = k16 * 8 * 4;
            uint32_t ah[4][4], al[4][4], bh[2][4], bl[2][4];
#pragma unroll
            for (int mt = 0; mt < 4; ++mt) {
                ldsm4(ah[mt], aAh + mt * (16 * SK * 4) + ko);
                ldsm4(al[mt], aAl + mt * (16 * SK * 4) + ko);
            }
#pragma unroll
            for (int np = 0; np < 2; ++np) {
                ldsm4(bh[np], aBh + np * (16 * SK * 4) + ko);
                ldsm4(bl[np], aBl + np * (16 * SK * 4) + ko);
            }
#pragma unroll
            for (int mt = 0; mt < 4; ++mt)
#pragma unroll
                for (int nt = 0; nt < 4; ++nt)
                    mma16816(c[mt][nt], ah[mt], &bh[nt >> 1][(nt & 1) * 2]);
#pragma unroll
            for (int mt = 0; mt < 4; ++mt)
#pragma unroll
                for (int nt = 0; nt < 4; ++nt)
                    mma16816(c[mt][nt], ah[mt], &bl[nt >> 1][(nt & 1) * 2]);
#pragma unroll
            for (int mt = 0; mt < 4; ++mt)
#pragma unroll
                for (int nt = 0; nt < 4; ++nt)
                    mma16816(c[mt][nt], al[mt], &bh[nt >> 1][(nt & 1) * 2]);
        }

        if (nx) stage(stg ^ 1);
        __syncthreads();
        stg ^= 1;
    }

    // epilogue
    if (mode == 3) {
        float rs0[4], rs1[4];
#pragma unroll
        for (int mt = 0; mt < 4; ++mt) { rs0[mt] = 0.0f; rs1[mt] = 0.0f; }
#pragma unroll
        for (int mt = 0; mt < 4; ++mt) {
#pragma unroll
            for (int nt = 0; nt < 4; ++nt) {
                const int r0 = bm + wm * 64 + mt * 16 + g;
                const int n0 = bn + wn * 32 + nt * 8 + tg * 2;
                float e0 = __expf(c[mt][nt][0] * scale);
                float e1 = __expf(c[mt][nt][1] * scale);
                float e2 = __expf(c[mt][nt][2] * scale);
                float e3 = __expf(c[mt][nt][3] * scale);
                *(float2*)(Cf + (size_t)r0 * ldc + n0)       = make_float2(e0, e1);
                *(float2*)(Cf + (size_t)(r0 + 8) * ldc + n0) = make_float2(e2, e3);
                rs0[mt] += e0 + e1;
                rs1[mt] += e2 + e3;
            }
        }
#pragma unroll
        for (int o = 1; o <= 2; o <<= 1) {
#pragma unroll
            for (int mt = 0; mt < 4; ++mt) {
                rs0[mt] += __shfl_xor_sync(0xffffffffu, rs0[mt], o);
                rs1[mt] += __shfl_xor_sync(0xffffffffu, rs1[mt], o);
            }
        }
        float* spart = (float*)(dsm + G_EXTRA);   // [128][4]
        if (tg == 0) {
#pragma unroll
            for (int mt = 0; mt < 4; ++mt) {
                spart[(wm * 64 + mt * 16 + g) * 4 + wn]     = rs0[mt];
                spart[(wm * 64 + mt * 16 + g + 8) * 4 + wn] = rs1[mt];
            }
        }
        __syncthreads();
        if (tid < 128) {
            const float* sp = spart + tid * 4;
            psum[(size_t)(bm + tid) * 32 + kb] = (sp[0] + sp[1]) + (sp[2] + sp[3]);
        }
    } else if (mode == 0) {
#pragma unroll
        for (int mt = 0; mt < 4; ++mt) {
#pragma unroll
            for (int nt = 0; nt < 4; ++nt) {
                const int r0 = bm + wm * 64 + mt * 16 + g;
                const int n0 = bn + wn * 32 + nt * 8 + tg * 2;
                const float2 bb = *(const float2*)&bias[n0];
                *(float2*)(Cf + (size_t)r0 * ldc + n0) =
                    make_float2(c[mt][nt][0] + bb.x, c[mt][nt][1] + bb.y);
                *(float2*)(Cf + (size_t)(r0 + 8) * ldc + n0) =
                    make_float2(c[mt][nt][2] + bb.x, c[mt][nt][3] + bb.y);
            }
        }
    } else if (mode == 1) {
#pragma unroll
        for (int mt = 0; mt < 4; ++mt) {
#pragma unroll
            for (int nt = 0; nt < 4; ++nt) {
                const int r0 = bm + wm * 64 + mt * 16 + g;
                const int n0 = bn + wn * 32 + nt * 8 + tg * 2;
                const float2 bb = *(const float2*)&bias[n0];
                const int hh = n0 >> 6, d = n0 & 63;
                const int b0 = r0 >> 11, s0 = r0 & 2047;
                const int s1 = (r0 + 8) & 2047;
                uint32_t h0, l0, h1, l1;
                split2(c[mt][nt][0] + bb.x, c[mt][nt][1] + bb.y, h0, l0);
                split2(c[mt][nt][2] + bb.x, c[mt][nt][3] + bb.y, h1, l1);
                const size_t o0 = ((size_t)(b0 * HEADS + hh) * SEQ + s0) * HDIM + d;
                const size_t o1 = ((size_t)(b0 * HEADS + hh) * SEQ + s1) * HDIM + d;
                *(uint32_t*)(Ch + o0) = h0;
                *(uint32_t*)(Cl + o0) = l0;
                *(uint32_t*)(Ch + o1) = h1;
                *(uint32_t*)(Cl + o1) = l1;
            }
        }
    } else {  // mode 2: V transposed split store [z][64][S]
#pragma unroll
        for (int mt = 0; mt < 4; ++mt) {
#pragma unroll
            for (int nt = 0; nt < 4; ++nt) {
                const int r0 = bm + wm * 64 + mt * 16 + g;
                const int n0 = bn + wn * 32 + nt * 8 + tg * 2;
                const float2 bb = *(const float2*)&bias[n0];
                const int hh = n0 >> 6, d = n0 & 63;
                const int b0 = r0 >> 11, s0 = r0 & 2047;
                const int s1 = (r0 + 8) & 2047;
                const size_t zb = (size_t)(b0 * HEADS + hh) * HDIM;
                float v00 = c[mt][nt][0] + bb.x, v01 = c[mt][nt][1] + bb.y;
                float v10 = c[mt][nt][2] + bb.x, v11 = c[mt][nt][3] + bb.y;
                __nv_bfloat16 h;
                h = __float2bfloat16(v00);
                Ch[(zb + d) * SEQ + s0] = h;
                Cl[(zb + d) * SEQ + s0] = __float2bfloat16(v00 - __bfloat162float(h));
                h = __float2bfloat16(v01);
                Ch[(zb + d + 1) * SEQ + s0] = h;
                Cl[(zb + d + 1) * SEQ + s0] = __float2bfloat16(v01 - __bfloat162float(h));
                h = __float2bfloat16(v10);
                Ch[(zb + d) * SEQ + s1] = h;
                Cl[(zb + d) * SEQ + s1] = __float2bfloat16(v10 - __bfloat162float(h));
                h = __float2bfloat16(v11);
                Ch[(zb + d + 1) * SEQ + s1] = h;
                Cl[(zb + d + 1) * SEQ + s1] = __float2bfloat16(v11 - __bfloat162float(h));
            }
        }
    }
}

// Generic wrapper with z-strides (scores mode 3, oproj mode 0)
__global__ __launch_bounds__(256, 1) void gemm_s_kernel(
    const __nv_bfloat16* __restrict__ Ah, const __nv_bfloat16* __restrict__ Al,
    const __nv_bfloat16* __restrict__ Bh, const __nv_bfloat16* __restrict__ Bl,
    const float* __restrict__ bias, float* __restrict__ Cf,
    int lda, int ldb, int ldc, int kdim,
    size_t sAz, size_t sBz, size_t sCz,
    int mode, float scale, float* __restrict__ psum)
{
    const int z = blockIdx.z;
    float* pz = psum ? (psum + (size_t)z * SEQ * 32) : nullptr;
    gemm_core_s(Ah + (size_t)z * sAz, Al + (size_t)z * sAz,
                Bh + (size_t)z * sBz, Bl + (size_t)z * sBz, bias,
                Cf + (size_t)z * sCz, nullptr, nullptr,
                lda, ldb, ldc, kdim, mode, scale,
                blockIdx.y * 128, blockIdx.x * 128, pz, blockIdx.x);
}

// Fused Q/K/V projection: z selects projection; outputs split bf16.
__global__ __launch_bounds__(256, 1) void qkv_proj_kernel(
    const float* __restrict__ qb, const float* __restrict__ kb,
    const float* __restrict__ vb)
{
    const int z = blockIdx.z;
    const __nv_bfloat16* Ah = g_Xh + (size_t)z * MTOT * EMBED;
    const __nv_bfloat16* Al = g_Xl + (size_t)z * MTOT * EMBED;
    const __nv_bfloat16* Bh = g_Wh + (size_t)z * EMBED * EMBED;
    const __nv_bfloat16* Bl = g_Wl + (size_t)z * EMBED * EMBED;
    const float* bias = (z == 0) ? qb : (z == 1) ? kb : vb;
    __nv_bfloat16 *Ch, *Cl;
    int mode;
    if (z == 0)      { Ch = g_Qh;  Cl = g_Ql;  mode = 1; }
    else if (z == 1) { Ch = g_Kh;  Cl = g_Kl;  mode = 1; }
    else             { Ch = g_Vth; Cl = g_Vtl; mode = 2; }
    gemm_core_s(Ah, Al, Bh, Bl, bias, nullptr, Ch, Cl,
                EMBED, EMBED, 0, EMBED, mode, 1.0f,
                blockIdx.y * 128, blockIdx.x * 128, nullptr, 0);
}

// ===========================================================================
// av: reads unnormalized exp scores, normalizes (writes back normalized attn
// in place), computes AO = P_norm @ V (V pre-split transposed), writes AO
// as split bf16 for the O projection.
// CTA tile 128(q) x 64(d), BK=32, double-buffered + ldmatrix.
// ===========================================================================
__global__ __launch_bounds__(256, 2) void av_mma_kernel(
    float* __restrict__ attn, const float* __restrict__ psum)
{
    extern __shared__ uint32_t dsm[];
    const uint32_t dsma = (uint32_t)__cvta_generic_to_shared(dsm);
    float* s_inv = (float*)(dsm + AV_EXTRA);   // [128]

    const int tid = threadIdx.x;
    const int w   = tid >> 5;
    const int lid = tid & 31;
    const int g   = lid >> 2;
    const int tg  = lid & 3;
    const int wm  = w >> 1;        // 0..3
    const int wn  = w & 1;         // 0..1

    const int a_r = (lid & 7) + ((lid >> 3) & 1) * 8;
    const int a_c = (lid >> 4) * 4;
    const int b_r = (lid & 7) + (lid >> 4) * 8;
    const int b_c = ((lid >> 3) & 1) * 4;

    const int z  = blockIdx.y;
    const int bm = blockIdx.x * 128;

    float* Wp = attn + (size_t)z * SEQ * SEQ + (size_t)bm * SEQ;
    const __nv_bfloat16* Vph = g_Vth + (size_t)z * HDIM * SEQ;
    const __nv_bfloat16* Vpl = g_Vtl + (size_t)z * HDIM * SEQ;

    // row inverse sums (deterministic reduction of 16 partials)
    if (tid < 128) {
        const float* pp = psum + ((size_t)z * SEQ + bm + tid) * 32;
        float s = 0.0f;
#pragma unroll
        for (int i = 0; i < 16; ++i) s += pp[i];
        s_inv[tid] = 1.0f / s;
    }
    __syncthreads();

    const int arow = tid >> 1;
    const int asu  = (tid & 1) * 8;
    float* apw = Wp + (size_t)arow * SEQ + asu * 2;
    const float inv = s_inv[arow];

    // V staging: 4 threads/row(d), 8 tokens each
    const int brow = tid >> 2;            // d 0..63
    const int bsu  = (tid & 3) * 4;       // u32 offset (8 bf16)
    const __nv_bfloat16* vph = Vph + (size_t)brow * SEQ + bsu * 2;
    const __nv_bfloat16* vpl = Vpl + (size_t)brow * SEQ + bsu * 2;

    float c[2][4][4];
#pragma unroll
    for (int mt = 0; mt < 2; ++mt)
#pragma unroll
        for (int nt = 0; nt < 4; ++nt)
#pragma unroll
            for (int i = 0; i < 4; ++i) c[mt][nt][i] = 0.0f;

    float4 pa[4];
    uint4  pvh, pvl;
#pragma unroll
    for (int j = 0; j < 4; ++j) pa[j] = *(const float4*)(apw + j * 4);
    pvh = *(const uint4*)(vph);
    pvl = *(const uint4*)(vpl);

    auto stage_tiles = [&](uint32_t* base, float* wb_ptr) {
        uint32_t* Ah = base;
        uint32_t* Al = base + 2560;
#pragma unroll
        for (int j = 0; j < 4; ++j) {
            float4 vv = make_float4(pa[j].x * inv, pa[j].y * inv,
                                    pa[j].z * inv, pa[j].w * inv);
            *(float4*)(wb_ptr + j * 4) = vv;   // normalized attn weights
            cvt_store_hl(&Ah[arow * SK + asu + j * 2], &Al[arow * SK + asu + j * 2], vv);
        }
        *(uint4*)&base[5120 + brow * SK + bsu] = pvh;
        *(uint4*)&base[6400 + brow * SK + bsu] = pvl;
    };

    stage_tiles(dsm, apw);
    __syncthreads();

    int stg = 0;
#pragma unroll 1
    for (int kt = 0; kt < SEQ; kt += 32) {
        const bool nx = (kt + 32 < SEQ);
        if (nx) {
#pragma unroll
            for (int j = 0; j < 4; ++j)
                pa[j] = *(const float4*)(apw + kt + 32 + j * 4);
            pvh = *(const uint4*)(vph + kt + 32);
            pvl = *(const uint4*)(vpl + kt + 32);
        }

        const uint32_t sb = dsma + stg * (AV_STAGE * 4);
        const uint32_t aAh = sb + ((wm * 32 + a_r) * SK + a_c) * 4;
        const uint32_t aAl = aAh + 2560 * 4;
        const uint32_t aBh = sb + 5120 * 4 + ((wn * 32 + b_r) * SK + b_c) * 4;
        const uint32_t aBl = aBh + 1280 * 4;

#pragma unroll
        for (int k16 = 0; k16 < 2; ++k16) {
            const uint32_t ko = k16 * 8 * 4;
            uint32_t ah[2][4], al[2][4], bh[2][4], bl[2][4];
#pragma unroll
            for (int mt = 0; mt < 2; ++mt) {
                ldsm4(ah[mt], aAh + mt * (16 * SK * 4) + ko);
                ldsm4(al[mt], aAl + mt * (16 * SK * 4) + ko);
            }
#pragma unroll
            for (int np = 0; np < 2; ++np) {
                ldsm4(bh[np], aBh + np * (16 * SK * 4) + ko);
                ldsm4(bl[np], aBl + np * (16 * SK * 4) + ko);
            }
#pragma unroll
            for (int mt = 0; mt < 2; ++mt)
#pragma unroll
                for (int nt = 0; nt < 4; ++nt)
                    mma16816(c[mt][nt], ah[mt], &bh[nt >> 1][(nt & 1) * 2]);
#pragma unroll
            for (int mt = 0; mt < 2; ++mt)
#pragma unroll
                for (int nt = 0; nt < 4; ++nt)
                    mma16816(c[mt][nt], ah[mt], &bl[nt >> 1][(nt & 1) * 2]);
#pragma unroll
            for (int mt = 0; mt < 2; ++mt)
#pragma unroll
                for (int nt = 0; nt < 4; ++nt)
                    mma16816(c[mt][nt], al[mt], &bh[nt >> 1][(nt & 1) * 2]);
        }

        if (nx)
            stage_tiles(dsm + (stg ^ 1) * AV_STAGE, apw + kt + 32);
        __syncthreads();
        stg ^= 1;
    }

    const int b = z >> 4, hh = z & 15;
#pragma unroll
    for (int mt = 0; mt < 2; ++mt) {
#pragma unroll
        for (int nt = 0; nt < 4; ++nt) {
            const int q0 = bm + wm * 32 + mt * 16 + g;
            const int d0 = wn * 32 + nt * 8 + tg * 2;
            const size_t o0 = ((size_t)(b * SEQ + q0)) * EMBED + hh * HDIM + d0;
            const size_t o1 = ((size_t)(b * SEQ + q0 + 8)) * EMBED + hh * HDIM + d0;
            uint32_t h0, l0, h1, l1;
            split2(c[mt][nt][0], c[mt][nt][1], h0, l0);
            split2(c[mt][nt][2], c[mt][nt][3], h1, l1);
            *(uint32_t*)(g_AOh + o0) = h0;
            *(uint32_t*)(g_AOl + o0) = l0;
            *(uint32_t*)(g_AOh + o1) = h1;
            *(uint32_t*)(g_AOl + o1) = l1;
        }
    }
}

// ---------------------------------------------------------------------------
// launch
// ---------------------------------------------------------------------------
extern "C" void kernel_launch(void* const* d_in, const int* in_sizes, int n_in,
                              void* d_out, int out_size)
{
    (void)in_sizes; (void)n_in; (void)out_size;
    const float* query = (const float*)d_in[0];
    const float* key   = (const float*)d_in[1];
    const float* value = (const float*)d_in[2];
    const float* q_w   = (const float*)d_in[3];
    const float* q_b   = (const float*)d_in[4];
    const float* k_w   = (const float*)d_in[5];
    const float* k_b   = (const float*)d_in[6];
    const float* v_w   = (const float*)d_in[7];
    const float* v_b   = (const float*)d_in[8];
    const float* o_w   = (const float*)d_in[9];
    const float* o_b   = (const float*)d_in[10];

    float* out  = (float*)d_out;                 // [B,S,E]
    float* attn = out + OUT_ELEMS;               // [B,H,S,S]

    float* pPS;
    cudaGetSymbolAddress((void**)&pPS, g_psum);
    __nv_bfloat16 *pAOh, *pAOl, *pQh, *pQl, *pKh, *pKl, *pWh, *pWl;
    cudaGetSymbolAddress((void**)&pAOh, g_AOh);
    cudaGetSymbolAddress((void**)&pAOl, g_AOl);
    cudaGetSymbolAddress((void**)&pQh, g_Qh);
    cudaGetSymbolAddress((void**)&pQl, g_Ql);
    cudaGetSymbolAddress((void**)&pKh, g_Kh);
    cudaGetSymbolAddress((void**)&pKl, g_Kl);
    cudaGetSymbolAddress((void**)&pWh, g_Wh);
    cudaGetSymbolAddress((void**)&pWl, g_Wl);

    static bool attr_done = false;
    if (!attr_done) {
        cudaFuncSetAttribute(qkv_proj_kernel,
                             cudaFuncAttributeMaxDynamicSharedMemorySize, GEMM_SMEM);
        cudaFuncSetAttribute(gemm_s_kernel,
                             cudaFuncAttributeMaxDynamicSharedMemorySize, GEMM_SMEM);
        cudaFuncSetAttribute(av_mma_kernel,
                             cudaFuncAttributeMaxDynamicSharedMemorySize, AV_SMEM);
        attr_done = true;
    }

    // 0) split all fp32 operands into bf16 hi/lo once
    dim3 pgrid(MTOT * EMBED / 4 / 256, 1, 7);    // (4096, 1, 7)
    prep_split_kernel<<<pgrid, 256>>>(query, key, value, q_w, k_w, v_w, o_w);

    // 1) fused Q/K/V projections (split-bf16 outputs; V transposed)
    dim3 qkvgrid(EMBED / 128, MTOT / 128, 3);    // (8, 32, 3)
    qkv_proj_kernel<<<qkvgrid, 256, GEMM_SMEM>>>(q_b, k_b, v_b);

    // 2) scores: attn[z] = exp((Q_z @ K_z^T) * 0.125) unnormalized + psum
    dim3 sgrid(SEQ / 128, SEQ / 128, ZTOT);      // (16, 16, 32)
    gemm_s_kernel<<<sgrid, 256, GEMM_SMEM>>>(pQh, pQl, pKh, pKl, nullptr, attn,
                                             HDIM, HDIM, SEQ, HDIM,
                                             (size_t)SEQ * HDIM, (size_t)SEQ * HDIM,
                                             (size_t)SEQ * SEQ, 3, 0.125f, pPS);

    // 3) av: normalize attn in place + AO = P @ V (split outputs)
    dim3 avgrid(SEQ / 128, ZTOT);                // (16, 32)
    av_mma_kernel<<<avgrid, 256, AV_SMEM>>>(attn, pPS);

    // 4) output projection (fp32 out + bias)
    dim3 ogrid(EMBED / 128, MTOT / 128, 1);      // (8, 32)
    gemm_s_kernel<<<ogrid, 256, GEMM_SMEM>>>(pAOh, pAOl,
                                             pWh + (size_t)3 * EMBED * EMBED,
                                             pWl + (size_t)3 * EMBED * EMBED,
                                             o_b, out,
                                             EMBED, EMBED, EMBED, EMBED, 0, 0, 0,
                                             0, 1.0f, nullptr);
}